// round 1
// baseline (speedup 1.0000x reference)
#include <cuda_runtime.h>
#include <math.h>

#define MTOT 4096     // B*S = 4*1024 tokens
#define DM   1024     // model dim
#define NH   16
#define DH   64

// Scratch buffers (allocation-free rule: __device__ globals)
__device__ float g_Q[MTOT * DM];
__device__ float g_K[MTOT * DM];
__device__ float g_V[MTOT * DM];
__device__ float g_attn[MTOT * DM];

// ---------------------------------------------------------------------------
// GEMM: C[M,N] = A[M,K] @ W[K,N] + bias[N]   (W stored row-major [in,out])
// 128x128 block, BK=8, 256 threads, 8x8 per thread, 1-deep global prefetch.
// ---------------------------------------------------------------------------
#define BM 128
#define BN 128
#define BK 8

__global__ __launch_bounds__(256, 2)
void gemm_bias_kernel(const float* __restrict__ A, const float* __restrict__ W,
                      const float* __restrict__ bias, float* __restrict__ C,
                      int M, int N, int K)
{
    __shared__ float As[BK][BM + 4];   // [k][m], padded
    __shared__ float Bs[BK][BN];       // [k][n]

    const int tid = threadIdx.x;
    const int tr  = tid >> 4;          // 0..15
    const int tc  = tid & 15;          // 0..15
    const int m0  = blockIdx.y * BM;
    const int n0  = blockIdx.x * BN;

    const int la_m  = tid >> 1;        // 0..127
    const int la_k4 = (tid & 1) * 4;   // 0 or 4
    const int lb_k  = tid >> 5;        // 0..7
    const int lb_n  = (tid & 31) * 4;  // 0..124

    float acc[8][8];
#pragma unroll
    for (int i = 0; i < 8; i++)
#pragma unroll
        for (int j = 0; j < 8; j++) acc[i][j] = 0.f;

    const float* Aptr = A + (size_t)(m0 + la_m) * K + la_k4;
    const float* Bptr = W + (size_t)lb_k * N + n0 + lb_n;

    float4 aR = *(const float4*)Aptr;
    float4 bR = *(const float4*)Bptr;

    const int ntiles = K / BK;
    for (int kt = 0; kt < ntiles; kt++) {
        As[la_k4 + 0][la_m] = aR.x;
        As[la_k4 + 1][la_m] = aR.y;
        As[la_k4 + 2][la_m] = aR.z;
        As[la_k4 + 3][la_m] = aR.w;
        *(float4*)&Bs[lb_k][lb_n] = bR;
        __syncthreads();

        if (kt + 1 < ntiles) {   // prefetch next tile into registers
            aR = *(const float4*)(Aptr + (kt + 1) * BK);
            bR = *(const float4*)(Bptr + (size_t)(kt + 1) * BK * N);
        }

#pragma unroll
        for (int k = 0; k < BK; k++) {
            float4 a0 = *(const float4*)&As[k][tr * 8];
            float4 a1 = *(const float4*)&As[k][tr * 8 + 4];
            float4 b0 = *(const float4*)&Bs[k][tc * 8];
            float4 b1 = *(const float4*)&Bs[k][tc * 8 + 4];
            float av[8] = {a0.x, a0.y, a0.z, a0.w, a1.x, a1.y, a1.z, a1.w};
            float bv[8] = {b0.x, b0.y, b0.z, b0.w, b1.x, b1.y, b1.z, b1.w};
#pragma unroll
            for (int i = 0; i < 8; i++)
#pragma unroll
                for (int j = 0; j < 8; j++)
                    acc[i][j] = fmaf(av[i], bv[j], acc[i][j]);
        }
        __syncthreads();
    }

#pragma unroll
    for (int i = 0; i < 8; i++) {
        const int m = m0 + tr * 8 + i;
        float* Crow = C + (size_t)m * N + n0 + tc * 8;
        const float* brow = bias + n0 + tc * 8;
#pragma unroll
        for (int j = 0; j < 8; j += 4) {
            float4 o;
            o.x = acc[i][j + 0] + brow[j + 0];
            o.y = acc[i][j + 1] + brow[j + 1];
            o.z = acc[i][j + 2] + brow[j + 2];
            o.w = acc[i][j + 3] + brow[j + 3];
            *(float4*)&Crow[j] = o;
        }
    }
}

// ---------------------------------------------------------------------------
// Flash attention (fp32): one CTA per (batch, head, 64-query tile).
// Q^T, K^T, P^T kept transposed in smem so all hot loads are LDS.128,
// conflict-free. Online softmax with per-row (m, l) replicated across the
// 16 lanes that share a row group; shfl-reduced.
// ---------------------------------------------------------------------------
#define PAD 68
#define SM_Q 0
#define SM_K (64 * PAD)
#define SM_P (2 * 64 * PAD)
#define SM_V (3 * 64 * PAD)
#define ATTN_SMEM ((3 * 64 * PAD + 64 * 64) * 4)   // 68608 bytes

__global__ __launch_bounds__(256)
void attention_kernel()
{
    extern __shared__ float smf[];
    float* QsT = smf + SM_Q;   // [d][r]  stride PAD
    float* KsT = smf + SM_K;   // [d][c]  stride PAD
    float* PsT = smf + SM_P;   // [j][r]  stride PAD
    float* Vs  = smf + SM_V;   // [j][c]  stride 64

    const int tid = threadIdx.x;
    const int tr  = tid >> 4;        // 0..15  -> rows tr*4..tr*4+3
    const int tc  = tid & 15;        // 0..15  -> cols tc*4..tc*4+3
    const int b   = blockIdx.z;
    const int h   = blockIdx.y;
    const int q0  = blockIdx.x * 64;

    // Load + transpose Q tile
    const float* Qg = g_Q + (size_t)(b * 1024 + q0) * DM + h * DH;
#pragma unroll
    for (int it = 0; it < 4; it++) {
        int idx = tid + it * 256;      // float4 index in 64x64 tile
        int r   = idx >> 4;
        int d4  = (idx & 15) * 4;
        float4 v = *(const float4*)(Qg + (size_t)r * DM + d4);
        QsT[(d4 + 0) * PAD + r] = v.x;
        QsT[(d4 + 1) * PAD + r] = v.y;
        QsT[(d4 + 2) * PAD + r] = v.z;
        QsT[(d4 + 3) * PAD + r] = v.w;
    }

    float o[4][4];
    float mrow[4], lrow[4];
#pragma unroll
    for (int i = 0; i < 4; i++) {
        mrow[i] = -1e30f;
        lrow[i] = 0.f;
#pragma unroll
        for (int j = 0; j < 4; j++) o[i][j] = 0.f;
    }

    for (int kt = 0; kt < 16; kt++) {
        __syncthreads();    // previous tile fully consumed before overwrite
        const float* Kg = g_K + (size_t)(b * 1024 + kt * 64) * DM + h * DH;
        const float* Vg = g_V + (size_t)(b * 1024 + kt * 64) * DM + h * DH;
#pragma unroll
        for (int it = 0; it < 4; it++) {
            int idx = tid + it * 256;
            int c   = idx >> 4;            // token within tile
            int d4  = (idx & 15) * 4;      // head-dim offset
            float4 kv = *(const float4*)(Kg + (size_t)c * DM + d4);
            KsT[(d4 + 0) * PAD + c] = kv.x;
            KsT[(d4 + 1) * PAD + c] = kv.y;
            KsT[(d4 + 2) * PAD + c] = kv.z;
            KsT[(d4 + 3) * PAD + c] = kv.w;
            float4 vv = *(const float4*)(Vg + (size_t)c * DM + d4);
            *(float4*)&Vs[c * 64 + d4] = vv;
        }
        __syncthreads();

        // S = Q K^T
        float s[4][4];
#pragma unroll
        for (int i = 0; i < 4; i++)
#pragma unroll
            for (int j = 0; j < 4; j++) s[i][j] = 0.f;

#pragma unroll 4
        for (int d = 0; d < 64; d++) {
            float4 a  = *(const float4*)&QsT[d * PAD + tr * 4];
            float4 k4 = *(const float4*)&KsT[d * PAD + tc * 4];
            float av[4] = {a.x, a.y, a.z, a.w};
            float bv[4] = {k4.x, k4.y, k4.z, k4.w};
#pragma unroll
            for (int i = 0; i < 4; i++)
#pragma unroll
                for (int j = 0; j < 4; j++)
                    s[i][j] = fmaf(av[i], bv[j], s[i][j]);
        }

        // online softmax
#pragma unroll
        for (int ri = 0; ri < 4; ri++) {
            float rm = -1e30f;
#pragma unroll
            for (int ci = 0; ci < 4; ci++) {
                s[ri][ci] *= 0.125f;       // 1/sqrt(64)
                rm = fmaxf(rm, s[ri][ci]);
            }
#pragma unroll
            for (int off = 8; off > 0; off >>= 1)
                rm = fmaxf(rm, __shfl_xor_sync(0xffffffffu, rm, off));
            float mnew = fmaxf(mrow[ri], rm);
            float corr = __expf(mrow[ri] - mnew);
            mrow[ri] = mnew;
            float rs = 0.f;
#pragma unroll
            for (int ci = 0; ci < 4; ci++) {
                float p = __expf(s[ri][ci] - mnew);
                s[ri][ci] = p;
                rs += p;
            }
#pragma unroll
            for (int off = 8; off > 0; off >>= 1)
                rs += __shfl_xor_sync(0xffffffffu, rs, off);
            lrow[ri] = lrow[ri] * corr + rs;
#pragma unroll
            for (int ci = 0; ci < 4; ci++) o[ri][ci] *= corr;
        }

        // store P transposed: PsT[col][row]
#pragma unroll
        for (int ci = 0; ci < 4; ci++) {
            float4 col;
            col.x = s[0][ci]; col.y = s[1][ci]; col.z = s[2][ci]; col.w = s[3][ci];
            *(float4*)&PsT[(tc * 4 + ci) * PAD + tr * 4] = col;
        }
        __syncthreads();

        // O += P V
#pragma unroll 4
        for (int j = 0; j < 64; j++) {
            float4 a  = *(const float4*)&PsT[j * PAD + tr * 4];
            float4 v4 = *(const float4*)&Vs[j * 64 + tc * 4];
            float av[4] = {a.x, a.y, a.z, a.w};
            float bv[4] = {v4.x, v4.y, v4.z, v4.w};
#pragma unroll
            for (int i = 0; i < 4; i++)
#pragma unroll
                for (int jj = 0; jj < 4; jj++)
                    o[i][jj] = fmaf(av[i], bv[jj], o[i][jj]);
        }
    }

    // normalize + write attn in [B, S, H*Dh] layout
#pragma unroll
    for (int ri = 0; ri < 4; ri++) {
        float inv = 1.f / lrow[ri];
        float4 outv;
        outv.x = o[ri][0] * inv;
        outv.y = o[ri][1] * inv;
        outv.z = o[ri][2] * inv;
        outv.w = o[ri][3] * inv;
        *(float4*)(g_attn + (size_t)(b * 1024 + q0 + tr * 4 + ri) * DM
                   + h * DH + tc * 4) = outv;
    }
}

// ---------------------------------------------------------------------------
extern "C" void kernel_launch(void* const* d_in, const int* in_sizes, int n_in,
                              void* d_out, int out_size)
{
    const float* q_in = (const float*)d_in[0];
    const float* k_in = (const float*)d_in[1];
    const float* v_in = (const float*)d_in[2];
    const float* Wq   = (const float*)d_in[3];
    const float* bq   = (const float*)d_in[4];
    const float* Wk   = (const float*)d_in[5];
    const float* bk   = (const float*)d_in[6];
    const float* Wv   = (const float*)d_in[7];
    const float* bv   = (const float*)d_in[8];
    const float* Wo   = (const float*)d_in[9];
    const float* bo   = (const float*)d_in[10];

    float *pQ, *pK, *pV, *pA;
    cudaGetSymbolAddress((void**)&pQ, g_Q);
    cudaGetSymbolAddress((void**)&pK, g_K);
    cudaGetSymbolAddress((void**)&pV, g_V);
    cudaGetSymbolAddress((void**)&pA, g_attn);

    dim3 gg(DM / BN, MTOT / BM);   // (8, 32)

    gemm_bias_kernel<<<gg, 256>>>(q_in, Wq, bq, pQ, MTOT, DM, DM);
    gemm_bias_kernel<<<gg, 256>>>(k_in, Wk, bk, pK, MTOT, DM, DM);
    gemm_bias_kernel<<<gg, 256>>>(v_in, Wv, bv, pV, MTOT, DM, DM);

    cudaFuncSetAttribute(attention_kernel,
                         cudaFuncAttributeMaxDynamicSharedMemorySize, ATTN_SMEM);
    attention_kernel<<<dim3(16, 16, 4), 256, ATTN_SMEM>>>();

    gemm_bias_kernel<<<gg, 256>>>(pA, Wo, bo, (float*)d_out, MTOT, DM, DM);
}

// round 6
// speedup vs baseline: 1.4930x; 1.4930x over previous
#include <cuda_runtime.h>
#include <cuda_bf16.h>
#include <cstdint>
#include <math.h>

// ============================ problem constants ============================
#define MTOT 4096
#define DM   1024
#define NH   16
#define DH   64

__device__ float g_Q[MTOT * DM];
__device__ float g_K[MTOT * DM];
__device__ float g_V[MTOT * DM];
__device__ float g_attn[MTOT * DM];
// transposed split weights: [N=1024][K=1024] bf16
__device__ __nv_bfloat16 g_wq_hi[DM * DM], g_wq_lo[DM * DM];
__device__ __nv_bfloat16 g_wk_hi[DM * DM], g_wk_lo[DM * DM];
__device__ __nv_bfloat16 g_wv_hi[DM * DM], g_wv_lo[DM * DM];
__device__ __nv_bfloat16 g_wo_hi[DM * DM], g_wo_lo[DM * DM];

// ============================ PTX helpers (sm_80-class only) ============================
__device__ __forceinline__ uint32_t smem_to_u32(const void* p) {
    uint32_t a;
    asm("{ .reg .u64 t; cvta.to.shared.u64 t, %1; cvt.u32.u64 %0, t; }"
        : "=r"(a) : "l"(p));
    return a;
}
__device__ __forceinline__ void ldmatrix_x4(uint32_t* r, uint32_t addr) {
    asm volatile("ldmatrix.sync.aligned.m8n8.x4.shared.b16 {%0,%1,%2,%3}, [%4];"
                 : "=r"(r[0]), "=r"(r[1]), "=r"(r[2]), "=r"(r[3]) : "r"(addr));
}
__device__ __forceinline__ void mma_bf16(float* c, const uint32_t* a, const uint32_t* b) {
    asm volatile(
        "mma.sync.aligned.m16n8k16.row.col.f32.bf16.bf16.f32 "
        "{%0,%1,%2,%3}, {%4,%5,%6,%7}, {%8,%9}, {%0,%1,%2,%3};"
        : "+f"(c[0]), "+f"(c[1]), "+f"(c[2]), "+f"(c[3])
        : "r"(a[0]), "r"(a[1]), "r"(a[2]), "r"(a[3]), "r"(b[0]), "r"(b[1]));
}
__device__ __forceinline__ void cp_async16(uint32_t saddr, const void* gaddr) {
    asm volatile("cp.async.ca.shared.global [%0], [%1], 16;"
                 :: "r"(saddr), "l"(gaddr) : "memory");
}
__device__ __forceinline__ void cp_async_commit() {
    asm volatile("cp.async.commit_group;" ::: "memory");
}
__device__ __forceinline__ void cp_async_wait0() {
    asm volatile("cp.async.wait_group 0;" ::: "memory");
}

// ---------------------------------------------------------------------------
// Weight transpose + bf16 split:  W[k][n] fp32  ->  T{hi,lo}[n][k] bf16
// ---------------------------------------------------------------------------
__global__ __launch_bounds__(256)
void transpose_w_kernel(const float* __restrict__ W,
                        __nv_bfloat16* __restrict__ Thi,
                        __nv_bfloat16* __restrict__ Tlo)
{
    __shared__ float t[32][33];
    const int n0 = blockIdx.x * 32, k0 = blockIdx.y * 32;
    const int tx = threadIdx.x, ty = threadIdx.y;   // 32 x 8
#pragma unroll
    for (int i = 0; i < 4; i++)
        t[ty + i * 8][tx] = W[(size_t)(k0 + ty + i * 8) * DM + n0 + tx];
    __syncthreads();
#pragma unroll
    for (int i = 0; i < 4; i++) {
        float x = t[tx][ty + i * 8];
        __nv_bfloat16 h = __float2bfloat16(x);
        __nv_bfloat16 l = __float2bfloat16(x - __bfloat162float(h));
        size_t o = (size_t)(n0 + ty + i * 8) * DM + k0 + tx;
        Thi[o] = h;
        Tlo[o] = l;
    }
}

// ---------------------------------------------------------------------------
// HMMA GEMM: C[4096,1024] = A[4096,1024] @ Wt^T + bias, split-bf16 x3.
// CTA 128x128, 8 warps (2x4), warp tile 64x32, K-chunks of 32, 2-stage smem.
// Smem rows padded to 80B -> conflict-free ldmatrix phases.
// ---------------------------------------------------------------------------
#define ROWB 80
#define OFF_AH 0
#define OFF_AL 10240
#define OFF_BH 20480
#define OFF_BL 30720
#define STAGE_BYTES 40960
#define GEMM_SMEM (2 * STAGE_BYTES)   // 81920

__global__ __launch_bounds__(256, 1)
void gemm_mma_kernel(const float* __restrict__ A,
                     const __nv_bfloat16* __restrict__ Bhi,
                     const __nv_bfloat16* __restrict__ Blo,
                     const float* __restrict__ bias,
                     float* __restrict__ C)
{
    extern __shared__ char smem[];
    const uint32_t smem_base = smem_to_u32(smem);
    const int tid  = threadIdx.x;
    const int wid  = tid >> 5;
    const int lane = tid & 31;
    const int wm   = wid >> 2;          // 0..1  (64-row slab)
    const int wn   = wid & 3;           // 0..3  (32-col slab)
    const int m0   = blockIdx.y * 128;
    const int n0   = blockIdx.x * 128;

    float acc[4][4][4];
#pragma unroll
    for (int i = 0; i < 4; i++)
#pragma unroll
        for (int j = 0; j < 4; j++)
#pragma unroll
            for (int k = 0; k < 4; k++) acc[i][j][k] = 0.f;

    // ---- helpers for load index mapping ----
    // A: 128 rows x 8 float4 groups; 1024 float4 -> 4 per thread
    // B: 2 halves x 128 rows x 4 16B pieces; 1024 pieces -> 4 per thread

    // ---- prologue: chunk 0 into stage 0 ----
    {
        const uint32_t st = smem_base;
#pragma unroll
        for (int i = 0; i < 4; i++) {
            int idx = tid + i * 256;
            int r = idx >> 3, g = idx & 7;
            float4 v = *(const float4*)(A + (size_t)(m0 + r) * DM + g * 4);
            __nv_bfloat16 h0 = __float2bfloat16(v.x), h1 = __float2bfloat16(v.y);
            __nv_bfloat16 h2 = __float2bfloat16(v.z), h3 = __float2bfloat16(v.w);
            __nv_bfloat16 l0 = __float2bfloat16(v.x - __bfloat162float(h0));
            __nv_bfloat16 l1 = __float2bfloat16(v.y - __bfloat162float(h1));
            __nv_bfloat16 l2 = __float2bfloat16(v.z - __bfloat162float(h2));
            __nv_bfloat16 l3 = __float2bfloat16(v.w - __bfloat162float(h3));
            uint2 hv, lv;
            hv.x = ((uint32_t)__bfloat16_as_ushort(h1) << 16) | __bfloat16_as_ushort(h0);
            hv.y = ((uint32_t)__bfloat16_as_ushort(h3) << 16) | __bfloat16_as_ushort(h2);
            lv.x = ((uint32_t)__bfloat16_as_ushort(l1) << 16) | __bfloat16_as_ushort(l0);
            lv.y = ((uint32_t)__bfloat16_as_ushort(l3) << 16) | __bfloat16_as_ushort(l2);
            *(uint2*)(smem + OFF_AH + r * ROWB + g * 8) = hv;
            *(uint2*)(smem + OFF_AL + r * ROWB + g * 8) = lv;
        }
#pragma unroll
        for (int i = 0; i < 4; i++) {
            int idx = tid + i * 256;
            int half = idx >> 9;
            int j = idx & 511;
            int r = j >> 2, cgp = j & 3;
            const __nv_bfloat16* src = (half ? Blo : Bhi)
                + (size_t)(n0 + r) * DM + cgp * 8;
            cp_async16(st + OFF_BH + half * 10240 + r * ROWB + cgp * 16, src);
        }
        cp_async_commit();
    }

    for (int kc = 0; kc < 32; kc++) {
        const int s = kc & 1;
        const uint32_t st = smem_base + s * STAGE_BYTES;

        // prefetch A fp32 for next chunk into registers (latency hidden by compute)
        float4 av[4];
        if (kc < 31) {
#pragma unroll
            for (int i = 0; i < 4; i++) {
                int idx = tid + i * 256;
                int r = idx >> 3, g = idx & 7;
                av[i] = *(const float4*)(A + (size_t)(m0 + r) * DM
                                         + (kc + 1) * 32 + g * 4);
            }
        }

        cp_async_wait0();
        __syncthreads();

        // issue B cp.async for next chunk into other stage (overlaps compute)
        if (kc < 31) {
            const uint32_t stn = smem_base + ((kc + 1) & 1) * STAGE_BYTES;
#pragma unroll
            for (int i = 0; i < 4; i++) {
                int idx = tid + i * 256;
                int half = idx >> 9;
                int j = idx & 511;
                int r = j >> 2, cgp = j & 3;
                const __nv_bfloat16* src = (half ? Blo : Bhi)
                    + (size_t)(n0 + r) * DM + (kc + 1) * 32 + cgp * 8;
                cp_async16(stn + OFF_BH + half * 10240 + r * ROWB + cgp * 16, src);
            }
            cp_async_commit();
        }

        // ---- compute chunk (2 k-steps of 16) ----
        const int arow  = wm * 64 + (lane & 15);
        const int acolb0 = (lane >> 4) * 16;           // byte offset within k-step
        const int bg    = lane >> 3;
        const int brow  = wn * 32 + ((bg & 2) ? 8 : 0) + (lane & 7);
        const int bcolb0 = (bg & 1) * 16;
#pragma unroll
        for (int ks = 0; ks < 2; ks++) {
            const int acolb = ks * 32 + acolb0;
            const int bcolb = ks * 32 + bcolb0;
            uint32_t ah[4][4], alr[4][4], bhf[4][2], blf[4][2];
#pragma unroll
            for (int mi = 0; mi < 4; mi++)
                ldmatrix_x4(ah[mi], st + OFF_AH + (arow + mi * 16) * ROWB + acolb);
#pragma unroll
            for (int p = 0; p < 2; p++) {
                uint32_t r4[4];
                ldmatrix_x4(r4, st + OFF_BH + (brow + p * 16) * ROWB + bcolb);
                bhf[p * 2][0] = r4[0]; bhf[p * 2][1] = r4[1];
                bhf[p * 2 + 1][0] = r4[2]; bhf[p * 2 + 1][1] = r4[3];
            }
#pragma unroll
            for (int mi = 0; mi < 4; mi++)
#pragma unroll
                for (int ni = 0; ni < 4; ni++)
                    mma_bf16(acc[mi][ni], ah[mi], bhf[ni]);
#pragma unroll
            for (int mi = 0; mi < 4; mi++)
                ldmatrix_x4(alr[mi], st + OFF_AL + (arow + mi * 16) * ROWB + acolb);
#pragma unroll
            for (int mi = 0; mi < 4; mi++)
#pragma unroll
                for (int ni = 0; ni < 4; ni++)
                    mma_bf16(acc[mi][ni], alr[mi], bhf[ni]);
#pragma unroll
            for (int p = 0; p < 2; p++) {
                uint32_t r4[4];
                ldmatrix_x4(r4, st + OFF_BL + (brow + p * 16) * ROWB + bcolb);
                blf[p * 2][0] = r4[0]; blf[p * 2][1] = r4[1];
                blf[p * 2 + 1][0] = r4[2]; blf[p * 2 + 1][1] = r4[3];
            }
#pragma unroll
            for (int mi = 0; mi < 4; mi++)
#pragma unroll
                for (int ni = 0; ni < 4; ni++)
                    mma_bf16(acc[mi][ni], ah[mi], blf[ni]);
        }

        // convert+store A for next chunk into other stage (after compute:
        // safe — all threads passed this iter's syncthreads, so nobody is
        // still reading the other stage; visibility via next iter's sync)
        if (kc < 31) {
            char* stn = smem + ((kc + 1) & 1) * STAGE_BYTES;
#pragma unroll
            for (int i = 0; i < 4; i++) {
                int idx = tid + i * 256;
                int r = idx >> 3, g = idx & 7;
                float4 v = av[i];
                __nv_bfloat16 h0 = __float2bfloat16(v.x), h1 = __float2bfloat16(v.y);
                __nv_bfloat16 h2 = __float2bfloat16(v.z), h3 = __float2bfloat16(v.w);
                __nv_bfloat16 l0 = __float2bfloat16(v.x - __bfloat162float(h0));
                __nv_bfloat16 l1 = __float2bfloat16(v.y - __bfloat162float(h1));
                __nv_bfloat16 l2 = __float2bfloat16(v.z - __bfloat162float(h2));
                __nv_bfloat16 l3 = __float2bfloat16(v.w - __bfloat162float(h3));
                uint2 hv, lv;
                hv.x = ((uint32_t)__bfloat16_as_ushort(h1) << 16) | __bfloat16_as_ushort(h0);
                hv.y = ((uint32_t)__bfloat16_as_ushort(h3) << 16) | __bfloat16_as_ushort(h2);
                lv.x = ((uint32_t)__bfloat16_as_ushort(l1) << 16) | __bfloat16_as_ushort(l0);
                lv.y = ((uint32_t)__bfloat16_as_ushort(l3) << 16) | __bfloat16_as_ushort(l2);
                *(uint2*)(stn + OFF_AH + r * ROWB + g * 8) = hv;
                *(uint2*)(stn + OFF_AL + r * ROWB + g * 8) = lv;
            }
        }
    }

    // ---- epilogue: registers -> global with bias ----
#pragma unroll
    for (int mi = 0; mi < 4; mi++) {
        const int r0 = m0 + wm * 64 + mi * 16 + (lane >> 2);
#pragma unroll
        for (int ni = 0; ni < 4; ni++) {
            const int col = n0 + wn * 32 + ni * 8 + (lane & 3) * 2;
            const float b0 = bias[col], b1 = bias[col + 1];
            float2 v0 = {acc[mi][ni][0] + b0, acc[mi][ni][1] + b1};
            float2 v1 = {acc[mi][ni][2] + b0, acc[mi][ni][3] + b1};
            *(float2*)(C + (size_t)r0 * DM + col) = v0;
            *(float2*)(C + (size_t)(r0 + 8) * DM + col) = v1;
        }
    }
}

// ---------------------------------------------------------------------------
// Flash attention (fp32) — unchanged
// ---------------------------------------------------------------------------
#define PAD 68
#define SM_Q 0
#define SM_K (64 * PAD)
#define SM_P (2 * 64 * PAD)
#define SM_V (3 * 64 * PAD)
#define ATTN_SMEM ((3 * 64 * PAD + 64 * 64) * 4)

__global__ __launch_bounds__(256)
void attention_kernel()
{
    extern __shared__ float smf[];
    float* QsT = smf + SM_Q;
    float* KsT = smf + SM_K;
    float* PsT = smf + SM_P;
    float* Vs  = smf + SM_V;

    const int tid = threadIdx.x;
    const int tr  = tid >> 4;
    const int tc  = tid & 15;
    const int b   = blockIdx.z;
    const int h   = blockIdx.y;
    const int q0  = blockIdx.x * 64;

    const float* Qg = g_Q + (size_t)(b * 1024 + q0) * DM + h * DH;
#pragma unroll
    for (int it = 0; it < 4; it++) {
        int idx = tid + it * 256;
        int r   = idx >> 4;
        int d4  = (idx & 15) * 4;
        float4 v = *(const float4*)(Qg + (size_t)r * DM + d4);
        QsT[(d4 + 0) * PAD + r] = v.x;
        QsT[(d4 + 1) * PAD + r] = v.y;
        QsT[(d4 + 2) * PAD + r] = v.z;
        QsT[(d4 + 3) * PAD + r] = v.w;
    }

    float o[4][4];
    float mrow[4], lrow[4];
#pragma unroll
    for (int i = 0; i < 4; i++) {
        mrow[i] = -1e30f;
        lrow[i] = 0.f;
#pragma unroll
        for (int j = 0; j < 4; j++) o[i][j] = 0.f;
    }

    for (int kt = 0; kt < 16; kt++) {
        __syncthreads();
        const float* Kg = g_K + (size_t)(b * 1024 + kt * 64) * DM + h * DH;
        const float* Vg = g_V + (size_t)(b * 1024 + kt * 64) * DM + h * DH;
#pragma unroll
        for (int it = 0; it < 4; it++) {
            int idx = tid + it * 256;
            int c   = idx >> 4;
            int d4  = (idx & 15) * 4;
            float4 kv = *(const float4*)(Kg + (size_t)c * DM + d4);
            KsT[(d4 + 0) * PAD + c] = kv.x;
            KsT[(d4 + 1) * PAD + c] = kv.y;
            KsT[(d4 + 2) * PAD + c] = kv.z;
            KsT[(d4 + 3) * PAD + c] = kv.w;
            float4 vv = *(const float4*)(Vg + (size_t)c * DM + d4);
            *(float4*)&Vs[c * 64 + d4] = vv;
        }
        __syncthreads();

        float s[4][4];
#pragma unroll
        for (int i = 0; i < 4; i++)
#pragma unroll
            for (int j = 0; j < 4; j++) s[i][j] = 0.f;

#pragma unroll 4
        for (int d = 0; d < 64; d++) {
            float4 a  = *(const float4*)&QsT[d * PAD + tr * 4];
            float4 k4 = *(const float4*)&KsT[d * PAD + tc * 4];
            float av[4] = {a.x, a.y, a.z, a.w};
            float bv[4] = {k4.x, k4.y, k4.z, k4.w};
#pragma unroll
            for (int i = 0; i < 4; i++)
#pragma unroll
                for (int j = 0; j < 4; j++)
                    s[i][j] = fmaf(av[i], bv[j], s[i][j]);
        }

#pragma unroll
        for (int ri = 0; ri < 4; ri++) {
            float rm = -1e30f;
#pragma unroll
            for (int ci = 0; ci < 4; ci++) {
                s[ri][ci] *= 0.125f;
                rm = fmaxf(rm, s[ri][ci]);
            }
#pragma unroll
            for (int off = 8; off > 0; off >>= 1)
                rm = fmaxf(rm, __shfl_xor_sync(0xffffffffu, rm, off));
            float mnew = fmaxf(mrow[ri], rm);
            float corr = __expf(mrow[ri] - mnew);
            mrow[ri] = mnew;
            float rs = 0.f;
#pragma unroll
            for (int ci = 0; ci < 4; ci++) {
                float p = __expf(s[ri][ci] - mnew);
                s[ri][ci] = p;
                rs += p;
            }
#pragma unroll
            for (int off = 8; off > 0; off >>= 1)
                rs += __shfl_xor_sync(0xffffffffu, rs, off);
            lrow[ri] = lrow[ri] * corr + rs;
#pragma unroll
            for (int ci = 0; ci < 4; ci++) o[ri][ci] *= corr;
        }

#pragma unroll
        for (int ci = 0; ci < 4; ci++) {
            float4 col;
            col.x = s[0][ci]; col.y = s[1][ci]; col.z = s[2][ci]; col.w = s[3][ci];
            *(float4*)&PsT[(tc * 4 + ci) * PAD + tr * 4] = col;
        }
        __syncthreads();

#pragma unroll 4
        for (int j = 0; j < 64; j++) {
            float4 a  = *(const float4*)&PsT[j * PAD + tr * 4];
            float4 v4 = *(const float4*)&Vs[j * 64 + tc * 4];
            float av[4] = {a.x, a.y, a.z, a.w};
            float bv[4] = {v4.x, v4.y, v4.z, v4.w};
#pragma unroll
            for (int i = 0; i < 4; i++)
#pragma unroll
                for (int jj = 0; jj < 4; jj++)
                    o[i][jj] = fmaf(av[i], bv[jj], o[i][jj]);
        }
    }

#pragma unroll
    for (int ri = 0; ri < 4; ri++) {
        float inv = 1.f / lrow[ri];
        float4 outv;
        outv.x = o[ri][0] * inv;
        outv.y = o[ri][1] * inv;
        outv.z = o[ri][2] * inv;
        outv.w = o[ri][3] * inv;
        *(float4*)(g_attn + (size_t)(b * 1024 + q0 + tr * 4 + ri) * DM
                   + h * DH + tc * 4) = outv;
    }
}

// ---------------------------------------------------------------------------
extern "C" void kernel_launch(void* const* d_in, const int* in_sizes, int n_in,
                              void* d_out, int out_size)
{
    const float* q_in = (const float*)d_in[0];
    const float* k_in = (const float*)d_in[1];
    const float* v_in = (const float*)d_in[2];
    const float* Wq   = (const float*)d_in[3];
    const float* bq   = (const float*)d_in[4];
    const float* Wk   = (const float*)d_in[5];
    const float* bk   = (const float*)d_in[6];
    const float* Wv   = (const float*)d_in[7];
    const float* bv   = (const float*)d_in[8];
    const float* Wo   = (const float*)d_in[9];
    const float* bo   = (const float*)d_in[10];

    float *pQ, *pK, *pV, *pA;
    cudaGetSymbolAddress((void**)&pQ, g_Q);
    cudaGetSymbolAddress((void**)&pK, g_K);
    cudaGetSymbolAddress((void**)&pV, g_V);
    cudaGetSymbolAddress((void**)&pA, g_attn);
    __nv_bfloat16 *wqh, *wql, *wkh, *wkl, *wvh, *wvl, *woh, *wol;
    cudaGetSymbolAddress((void**)&wqh, g_wq_hi);
    cudaGetSymbolAddress((void**)&wql, g_wq_lo);
    cudaGetSymbolAddress((void**)&wkh, g_wk_hi);
    cudaGetSymbolAddress((void**)&wkl, g_wk_lo);
    cudaGetSymbolAddress((void**)&wvh, g_wv_hi);
    cudaGetSymbolAddress((void**)&wvl, g_wv_lo);
    cudaGetSymbolAddress((void**)&woh, g_wo_hi);
    cudaGetSymbolAddress((void**)&wol, g_wo_lo);

    cudaFuncSetAttribute(gemm_mma_kernel,
                         cudaFuncAttributeMaxDynamicSharedMemorySize, GEMM_SMEM);
    cudaFuncSetAttribute(attention_kernel,
                         cudaFuncAttributeMaxDynamicSharedMemorySize, ATTN_SMEM);

    dim3 tg(32, 32), tb(32, 8);
    transpose_w_kernel<<<tg, tb>>>(Wq, wqh, wql);
    transpose_w_kernel<<<tg, tb>>>(Wk, wkh, wkl);
    transpose_w_kernel<<<tg, tb>>>(Wv, wvh, wvl);
    transpose_w_kernel<<<tg, tb>>>(Wo, woh, wol);

    dim3 gg(DM / 128, MTOT / 128);   // (8, 32)
    gemm_mma_kernel<<<gg, 256, GEMM_SMEM>>>(q_in, wqh, wql, bq, pQ);
    gemm_mma_kernel<<<gg, 256, GEMM_SMEM>>>(k_in, wkh, wkl, bk, pK);
    gemm_mma_kernel<<<gg, 256, GEMM_SMEM>>>(v_in, wvh, wvl, bv, pV);

    attention_kernel<<<dim3(16, 16, 4), 256, ATTN_SMEM>>>();

    gemm_mma_kernel<<<gg, 256, GEMM_SMEM>>>(pA, woh, wol, bo, (float*)d_out);
}

// round 11
// speedup vs baseline: 2.3238x; 1.5564x over previous
#include <cuda_runtime.h>
#include <cuda_bf16.h>
#include <cstdint>
#include <math.h>

// ============================ problem constants ============================
#define MTOT 4096
#define DM   1024
#define NH   16
#define DH   64

__device__ float g_Q[MTOT * DM];
__device__ float g_K[MTOT * DM];
__device__ float g_V[MTOT * DM];
__device__ float g_attn[MTOT * DM];
// transposed split weights: [N=1024][K=1024] bf16
__device__ __nv_bfloat16 g_wq_hi[DM * DM], g_wq_lo[DM * DM];
__device__ __nv_bfloat16 g_wk_hi[DM * DM], g_wk_lo[DM * DM];
__device__ __nv_bfloat16 g_wv_hi[DM * DM], g_wv_lo[DM * DM];
__device__ __nv_bfloat16 g_wo_hi[DM * DM], g_wo_lo[DM * DM];

// ============================ PTX helpers (sm_80-class only) ============================
__device__ __forceinline__ uint32_t smem_to_u32(const void* p) {
    uint32_t a;
    asm("{ .reg .u64 t; cvta.to.shared.u64 t, %1; cvt.u32.u64 %0, t; }"
        : "=r"(a) : "l"(p));
    return a;
}
__device__ __forceinline__ void ldmatrix_x4(uint32_t* r, uint32_t addr) {
    asm volatile("ldmatrix.sync.aligned.m8n8.x4.shared.b16 {%0,%1,%2,%3}, [%4];"
                 : "=r"(r[0]), "=r"(r[1]), "=r"(r[2]), "=r"(r[3]) : "r"(addr));
}
__device__ __forceinline__ void ldmatrix_x4_trans(uint32_t* r, uint32_t addr) {
    asm volatile("ldmatrix.sync.aligned.m8n8.x4.trans.shared.b16 {%0,%1,%2,%3}, [%4];"
                 : "=r"(r[0]), "=r"(r[1]), "=r"(r[2]), "=r"(r[3]) : "r"(addr));
}
__device__ __forceinline__ void mma_bf16(float* c, const uint32_t* a, const uint32_t* b) {
    asm volatile(
        "mma.sync.aligned.m16n8k16.row.col.f32.bf16.bf16.f32 "
        "{%0,%1,%2,%3}, {%4,%5,%6,%7}, {%8,%9}, {%0,%1,%2,%3};"
        : "+f"(c[0]), "+f"(c[1]), "+f"(c[2]), "+f"(c[3])
        : "r"(a[0]), "r"(a[1]), "r"(a[2]), "r"(a[3]), "r"(b[0]), "r"(b[1]));
}
__device__ __forceinline__ void cp_async16(uint32_t saddr, const void* gaddr) {
    asm volatile("cp.async.ca.shared.global [%0], [%1], 16;"
                 :: "r"(saddr), "l"(gaddr) : "memory");
}
__device__ __forceinline__ void cp_async_commit() {
    asm volatile("cp.async.commit_group;" ::: "memory");
}
__device__ __forceinline__ void cp_async_wait0() {
    asm volatile("cp.async.wait_group 0;" ::: "memory");
}
// pack (lo, hi) floats -> bf16x2 (hi in upper 16 bits)
__device__ __forceinline__ uint32_t pack_bf16x2(float lo, float hi) {
    uint32_t r;
    asm("cvt.rn.bf16x2.f32 %0, %1, %2;" : "=r"(r) : "f"(hi), "f"(lo));
    return r;
}

// ---------------------------------------------------------------------------
// Weight transpose + bf16 split:  W[k][n] fp32  ->  T{hi,lo}[n][k] bf16
// ---------------------------------------------------------------------------
__global__ __launch_bounds__(256)
void transpose_w_kernel(const float* __restrict__ W,
                        __nv_bfloat16* __restrict__ Thi,
                        __nv_bfloat16* __restrict__ Tlo)
{
    __shared__ float t[32][33];
    const int n0 = blockIdx.x * 32, k0 = blockIdx.y * 32;
    const int tx = threadIdx.x, ty = threadIdx.y;   // 32 x 8
#pragma unroll
    for (int i = 0; i < 4; i++)
        t[ty + i * 8][tx] = W[(size_t)(k0 + ty + i * 8) * DM + n0 + tx];
    __syncthreads();
#pragma unroll
    for (int i = 0; i < 4; i++) {
        float x = t[tx][ty + i * 8];
        __nv_bfloat16 h = __float2bfloat16(x);
        __nv_bfloat16 l = __float2bfloat16(x - __bfloat162float(h));
        size_t o = (size_t)(n0 + ty + i * 8) * DM + k0 + tx;
        Thi[o] = h;
        Tlo[o] = l;
    }
}

// ---------------------------------------------------------------------------
// HMMA GEMM (unchanged, known-good): CTA 128x128, split-bf16 x3.
// ---------------------------------------------------------------------------
#define ROWB 80
#define OFF_AH 0
#define OFF_AL 10240
#define OFF_BH 20480
#define OFF_BL 30720
#define STAGE_BYTES 40960
#define GEMM_SMEM (2 * STAGE_BYTES)

__global__ __launch_bounds__(256, 1)
void gemm_mma_kernel(const float* __restrict__ A,
                     const __nv_bfloat16* __restrict__ Bhi,
                     const __nv_bfloat16* __restrict__ Blo,
                     const float* __restrict__ bias,
                     float* __restrict__ C)
{
    extern __shared__ char smem[];
    const uint32_t smem_base = smem_to_u32(smem);
    const int tid  = threadIdx.x;
    const int wid  = tid >> 5;
    const int lane = tid & 31;
    const int wm   = wid >> 2;
    const int wn   = wid & 3;
    const int m0   = blockIdx.y * 128;
    const int n0   = blockIdx.x * 128;

    float acc[4][4][4];
#pragma unroll
    for (int i = 0; i < 4; i++)
#pragma unroll
        for (int j = 0; j < 4; j++)
#pragma unroll
            for (int k = 0; k < 4; k++) acc[i][j][k] = 0.f;

    {
        const uint32_t st = smem_base;
#pragma unroll
        for (int i = 0; i < 4; i++) {
            int idx = tid + i * 256;
            int r = idx >> 3, g = idx & 7;
            float4 v = *(const float4*)(A + (size_t)(m0 + r) * DM + g * 4);
            __nv_bfloat16 h0 = __float2bfloat16(v.x), h1 = __float2bfloat16(v.y);
            __nv_bfloat16 h2 = __float2bfloat16(v.z), h3 = __float2bfloat16(v.w);
            __nv_bfloat16 l0 = __float2bfloat16(v.x - __bfloat162float(h0));
            __nv_bfloat16 l1 = __float2bfloat16(v.y - __bfloat162float(h1));
            __nv_bfloat16 l2 = __float2bfloat16(v.z - __bfloat162float(h2));
            __nv_bfloat16 l3 = __float2bfloat16(v.w - __bfloat162float(h3));
            uint2 hv, lv;
            hv.x = ((uint32_t)__bfloat16_as_ushort(h1) << 16) | __bfloat16_as_ushort(h0);
            hv.y = ((uint32_t)__bfloat16_as_ushort(h3) << 16) | __bfloat16_as_ushort(h2);
            lv.x = ((uint32_t)__bfloat16_as_ushort(l1) << 16) | __bfloat16_as_ushort(l0);
            lv.y = ((uint32_t)__bfloat16_as_ushort(l3) << 16) | __bfloat16_as_ushort(l2);
            *(uint2*)(smem + OFF_AH + r * ROWB + g * 8) = hv;
            *(uint2*)(smem + OFF_AL + r * ROWB + g * 8) = lv;
        }
#pragma unroll
        for (int i = 0; i < 4; i++) {
            int idx = tid + i * 256;
            int half = idx >> 9;
            int j = idx & 511;
            int r = j >> 2, cgp = j & 3;
            const __nv_bfloat16* src = (half ? Blo : Bhi)
                + (size_t)(n0 + r) * DM + cgp * 8;
            cp_async16(st + OFF_BH + half * 10240 + r * ROWB + cgp * 16, src);
        }
        cp_async_commit();
    }

    for (int kc = 0; kc < 32; kc++) {
        const int s = kc & 1;
        const uint32_t st = smem_base + s * STAGE_BYTES;

        float4 av[4];
        if (kc < 31) {
#pragma unroll
            for (int i = 0; i < 4; i++) {
                int idx = tid + i * 256;
                int r = idx >> 3, g = idx & 7;
                av[i] = *(const float4*)(A + (size_t)(m0 + r) * DM
                                         + (kc + 1) * 32 + g * 4);
            }
        }

        cp_async_wait0();
        __syncthreads();

        if (kc < 31) {
            const uint32_t stn = smem_base + ((kc + 1) & 1) * STAGE_BYTES;
#pragma unroll
            for (int i = 0; i < 4; i++) {
                int idx = tid + i * 256;
                int half = idx >> 9;
                int j = idx & 511;
                int r = j >> 2, cgp = j & 3;
                const __nv_bfloat16* src = (half ? Blo : Bhi)
                    + (size_t)(n0 + r) * DM + (kc + 1) * 32 + cgp * 8;
                cp_async16(stn + OFF_BH + half * 10240 + r * ROWB + cgp * 16, src);
            }
            cp_async_commit();
        }

        const int arow  = wm * 64 + (lane & 15);
        const int acolb0 = (lane >> 4) * 16;
        const int bg    = lane >> 3;
        const int brow  = wn * 32 + ((bg & 2) ? 8 : 0) + (lane & 7);
        const int bcolb0 = (bg & 1) * 16;
#pragma unroll
        for (int ks = 0; ks < 2; ks++) {
            const int acolb = ks * 32 + acolb0;
            const int bcolb = ks * 32 + bcolb0;
            uint32_t ah[4][4], alr[4][4], bhf[4][2], blf[4][2];
#pragma unroll
            for (int mi = 0; mi < 4; mi++)
                ldmatrix_x4(ah[mi], st + OFF_AH + (arow + mi * 16) * ROWB + acolb);
#pragma unroll
            for (int p = 0; p < 2; p++) {
                uint32_t r4[4];
                ldmatrix_x4(r4, st + OFF_BH + (brow + p * 16) * ROWB + bcolb);
                bhf[p * 2][0] = r4[0]; bhf[p * 2][1] = r4[1];
                bhf[p * 2 + 1][0] = r4[2]; bhf[p * 2 + 1][1] = r4[3];
            }
#pragma unroll
            for (int mi = 0; mi < 4; mi++)
#pragma unroll
                for (int ni = 0; ni < 4; ni++)
                    mma_bf16(acc[mi][ni], ah[mi], bhf[ni]);
#pragma unroll
            for (int mi = 0; mi < 4; mi++)
                ldmatrix_x4(alr[mi], st + OFF_AL + (arow + mi * 16) * ROWB + acolb);
#pragma unroll
            for (int mi = 0; mi < 4; mi++)
#pragma unroll
                for (int ni = 0; ni < 4; ni++)
                    mma_bf16(acc[mi][ni], alr[mi], bhf[ni]);
#pragma unroll
            for (int p = 0; p < 2; p++) {
                uint32_t r4[4];
                ldmatrix_x4(r4, st + OFF_BL + (brow + p * 16) * ROWB + bcolb);
                blf[p * 2][0] = r4[0]; blf[p * 2][1] = r4[1];
                blf[p * 2 + 1][0] = r4[2]; blf[p * 2 + 1][1] = r4[3];
            }
#pragma unroll
            for (int mi = 0; mi < 4; mi++)
#pragma unroll
                for (int ni = 0; ni < 4; ni++)
                    mma_bf16(acc[mi][ni], ah[mi], blf[ni]);
        }

        if (kc < 31) {
            char* stn = smem + ((kc + 1) & 1) * STAGE_BYTES;
#pragma unroll
            for (int i = 0; i < 4; i++) {
                int idx = tid + i * 256;
                int r = idx >> 3, g = idx & 7;
                float4 v = av[i];
                __nv_bfloat16 h0 = __float2bfloat16(v.x), h1 = __float2bfloat16(v.y);
                __nv_bfloat16 h2 = __float2bfloat16(v.z), h3 = __float2bfloat16(v.w);
                __nv_bfloat16 l0 = __float2bfloat16(v.x - __bfloat162float(h0));
                __nv_bfloat16 l1 = __float2bfloat16(v.y - __bfloat162float(h1));
                __nv_bfloat16 l2 = __float2bfloat16(v.z - __bfloat162float(h2));
                __nv_bfloat16 l3 = __float2bfloat16(v.w - __bfloat162float(h3));
                uint2 hv, lv;
                hv.x = ((uint32_t)__bfloat16_as_ushort(h1) << 16) | __bfloat16_as_ushort(h0);
                hv.y = ((uint32_t)__bfloat16_as_ushort(h3) << 16) | __bfloat16_as_ushort(h2);
                lv.x = ((uint32_t)__bfloat16_as_ushort(l1) << 16) | __bfloat16_as_ushort(l0);
                lv.y = ((uint32_t)__bfloat16_as_ushort(l3) << 16) | __bfloat16_as_ushort(l2);
                *(uint2*)(stn + OFF_AH + r * ROWB + g * 8) = hv;
                *(uint2*)(stn + OFF_AL + r * ROWB + g * 8) = lv;
            }
        }
    }

#pragma unroll
    for (int mi = 0; mi < 4; mi++) {
        const int r0 = m0 + wm * 64 + mi * 16 + (lane >> 2);
#pragma unroll
        for (int ni = 0; ni < 4; ni++) {
            const int col = n0 + wn * 32 + ni * 8 + (lane & 3) * 2;
            const float b0 = bias[col], b1 = bias[col + 1];
            float2 v0 = {acc[mi][ni][0] + b0, acc[mi][ni][1] + b1};
            float2 v1 = {acc[mi][ni][2] + b0, acc[mi][ni][3] + b1};
            *(float2*)(C + (size_t)r0 * DM + col) = v0;
            *(float2*)(C + (size_t)(r0 + 8) * DM + col) = v1;
        }
    }
}

// ---------------------------------------------------------------------------
// Flash attention v2 — HMMA bf16 split-precision (placeholder-write bug fixed).
// ---------------------------------------------------------------------------
#define AROWB 144
#define AQ_H 0
#define AQ_L (128 * AROWB)
#define AK_H (2 * 128 * AROWB)
#define AK_L (AK_H + 64 * AROWB)
#define AV_H (AK_L + 64 * AROWB)
#define AV_L (AV_H + 64 * AROWB)
#define ATTN2_SMEM (AV_L + 64 * AROWB)   // 73728

__global__ __launch_bounds__(256)
void attention_mma_kernel()
{
    extern __shared__ char smem[];
    const uint32_t smem_base = smem_to_u32(smem);
    const int tid  = threadIdx.x;
    const int wid  = tid >> 5;
    const int lane = tid & 31;
    const int b    = blockIdx.z;
    const int h    = blockIdx.y;
    const int q0   = blockIdx.x * 128;

    // ---- stage Q tile (128 x 64) as hi/lo bf16 ----
    const float* Qg = g_Q + (size_t)(b * 1024 + q0) * DM + h * DH;
#pragma unroll
    for (int i = 0; i < 8; i++) {
        int idx = tid + i * 256;
        int r = idx >> 4, d4 = idx & 15;
        float4 v = *(const float4*)(Qg + (size_t)r * DM + d4 * 4);
        __nv_bfloat16 h0 = __float2bfloat16(v.x), h1 = __float2bfloat16(v.y);
        __nv_bfloat16 h2 = __float2bfloat16(v.z), h3 = __float2bfloat16(v.w);
        __nv_bfloat16 l0 = __float2bfloat16(v.x - __bfloat162float(h0));
        __nv_bfloat16 l1 = __float2bfloat16(v.y - __bfloat162float(h1));
        __nv_bfloat16 l2 = __float2bfloat16(v.z - __bfloat162float(h2));
        __nv_bfloat16 l3 = __float2bfloat16(v.w - __bfloat162float(h3));
        uint2 hv, lv;
        hv.x = ((uint32_t)__bfloat16_as_ushort(h1) << 16) | __bfloat16_as_ushort(h0);
        hv.y = ((uint32_t)__bfloat16_as_ushort(h3) << 16) | __bfloat16_as_ushort(h2);
        lv.x = ((uint32_t)__bfloat16_as_ushort(l1) << 16) | __bfloat16_as_ushort(l0);
        lv.y = ((uint32_t)__bfloat16_as_ushort(l3) << 16) | __bfloat16_as_ushort(l2);
        *(uint2*)(smem + AQ_H + r * AROWB + d4 * 8) = hv;
        *(uint2*)(smem + AQ_L + r * AROWB + d4 * 8) = lv;
    }

    float oacc[8][4];
    float mrow[2], lrow[2];
#pragma unroll
    for (int t = 0; t < 8; t++)
#pragma unroll
        for (int c = 0; c < 4; c++) oacc[t][c] = 0.f;
    mrow[0] = mrow[1] = -1e30f;
    lrow[0] = lrow[1] = 0.f;

    const uint32_t aH = smem_base + AQ_H + (wid * 16 + (lane & 15)) * AROWB + (lane >> 4) * 16;
    const uint32_t aL = smem_base + AQ_L + (wid * 16 + (lane & 15)) * AROWB + (lane >> 4) * 16;
    const int bg = lane >> 3;
    const int brow_off = ((bg & 2) ? 8 : 0) + (lane & 7);
    const int bcolb = (bg & 1) * 16;
    const uint32_t vrow_addr = (lane & 15) * AROWB + (lane >> 4) * 16;

    for (int kt = 0; kt < 16; kt++) {
        __syncthreads();
        const float* Kg = g_K + (size_t)(b * 1024 + kt * 64) * DM + h * DH;
        const float* Vg = g_V + (size_t)(b * 1024 + kt * 64) * DM + h * DH;
#pragma unroll
        for (int i = 0; i < 4; i++) {
            int idx = tid + i * 256;
            int r = idx >> 4, d4 = idx & 15;
            float4 v = *(const float4*)(Kg + (size_t)r * DM + d4 * 4);
            __nv_bfloat16 h0 = __float2bfloat16(v.x), h1 = __float2bfloat16(v.y);
            __nv_bfloat16 h2 = __float2bfloat16(v.z), h3 = __float2bfloat16(v.w);
            __nv_bfloat16 l0 = __float2bfloat16(v.x - __bfloat162float(h0));
            __nv_bfloat16 l1 = __float2bfloat16(v.y - __bfloat162float(h1));
            __nv_bfloat16 l2 = __float2bfloat16(v.z - __bfloat162float(h2));
            __nv_bfloat16 l3 = __float2bfloat16(v.w - __bfloat162float(h3));
            uint2 hv, lv;
            hv.x = ((uint32_t)__bfloat16_as_ushort(h1) << 16) | __bfloat16_as_ushort(h0);
            hv.y = ((uint32_t)__bfloat16_as_ushort(h3) << 16) | __bfloat16_as_ushort(h2);
            lv.x = ((uint32_t)__bfloat16_as_ushort(l1) << 16) | __bfloat16_as_ushort(l0);
            lv.y = ((uint32_t)__bfloat16_as_ushort(l3) << 16) | __bfloat16_as_ushort(l2);
            *(uint2*)(smem + AK_H + r * AROWB + d4 * 8) = hv;
            *(uint2*)(smem + AK_L + r * AROWB + d4 * 8) = lv;
            float4 w = *(const float4*)(Vg + (size_t)r * DM + d4 * 4);
            h0 = __float2bfloat16(w.x); h1 = __float2bfloat16(w.y);
            h2 = __float2bfloat16(w.z); h3 = __float2bfloat16(w.w);
            l0 = __float2bfloat16(w.x - __bfloat162float(h0));
            l1 = __float2bfloat16(w.y - __bfloat162float(h1));
            l2 = __float2bfloat16(w.z - __bfloat162float(h2));
            l3 = __float2bfloat16(w.w - __bfloat162float(h3));
            hv.x = ((uint32_t)__bfloat16_as_ushort(h1) << 16) | __bfloat16_as_ushort(h0);
            hv.y = ((uint32_t)__bfloat16_as_ushort(h3) << 16) | __bfloat16_as_ushort(h2);
            lv.x = ((uint32_t)__bfloat16_as_ushort(l1) << 16) | __bfloat16_as_ushort(l0);
            lv.y = ((uint32_t)__bfloat16_as_ushort(l3) << 16) | __bfloat16_as_ushort(l2);
            *(uint2*)(smem + AV_H + r * AROWB + d4 * 8) = hv;
            *(uint2*)(smem + AV_L + r * AROWB + d4 * 8) = lv;
        }
        __syncthreads();

        // ---- S = Q K^T (split x3) ----
        float sacc[8][4];
#pragma unroll
        for (int t = 0; t < 8; t++)
#pragma unroll
            for (int c = 0; c < 4; c++) sacc[t][c] = 0.f;

#pragma unroll
        for (int ks = 0; ks < 4; ks++) {
            uint32_t qh[4], ql[4];
            ldmatrix_x4(qh, aH + ks * 32);
            ldmatrix_x4(ql, aL + ks * 32);
#pragma unroll
            for (int nt = 0; nt < 4; nt++) {
                uint32_t kh[4], kl[4];
                uint32_t baddr = smem_base + AK_H + (nt * 16 + brow_off) * AROWB + ks * 32 + bcolb;
                ldmatrix_x4(kh, baddr);
                ldmatrix_x4(kl, baddr + (AK_L - AK_H));
                mma_bf16(sacc[2 * nt],     qh, kh + 0);
                mma_bf16(sacc[2 * nt + 1], qh, kh + 2);
                mma_bf16(sacc[2 * nt],     qh, kl + 0);
                mma_bf16(sacc[2 * nt + 1], qh, kl + 2);
                mma_bf16(sacc[2 * nt],     ql, kh + 0);
                mma_bf16(sacc[2 * nt + 1], ql, kh + 2);
            }
        }

        // ---- online softmax ----
#pragma unroll
        for (int half = 0; half < 2; half++) {
            const int c0 = half * 2;
            float rm = -1e30f;
#pragma unroll
            for (int t = 0; t < 8; t++) {
                sacc[t][c0]     *= 0.125f;
                sacc[t][c0 + 1] *= 0.125f;
                rm = fmaxf(rm, fmaxf(sacc[t][c0], sacc[t][c0 + 1]));
            }
            rm = fmaxf(rm, __shfl_xor_sync(0xffffffffu, rm, 1));
            rm = fmaxf(rm, __shfl_xor_sync(0xffffffffu, rm, 2));
            float mnew = fmaxf(mrow[half], rm);
            float corr = __expf(mrow[half] - mnew);
            mrow[half] = mnew;
            float rs = 0.f;
#pragma unroll
            for (int t = 0; t < 8; t++) {
                float p0 = __expf(sacc[t][c0] - mnew);
                float p1 = __expf(sacc[t][c0 + 1] - mnew);
                sacc[t][c0] = p0;
                sacc[t][c0 + 1] = p1;
                rs += p0 + p1;
            }
            rs += __shfl_xor_sync(0xffffffffu, rs, 1);
            rs += __shfl_xor_sync(0xffffffffu, rs, 2);
            lrow[half] = lrow[half] * corr + rs;
#pragma unroll
            for (int t = 0; t < 8; t++) {
                oacc[t][c0]     *= corr;
                oacc[t][c0 + 1] *= corr;
            }
        }

        // ---- O += P V (split x3); P A-fragments built from sacc ----
        // a0=(row, tok 16j+0-7)=sacc[2j][0,1]   a1=(row+8, same)=sacc[2j][2,3]
        // a2=(row, tok 16j+8-15)=sacc[2j+1][0,1] a3=(row+8, same)=sacc[2j+1][2,3]
#pragma unroll
        for (int j = 0; j < 4; j++) {
            uint32_t ph[4], pl[4];
#pragma unroll
            for (int q = 0; q < 4; q++) {
                const int t = 2 * j + (q >> 1);
                const int c = (q & 1) * 2;
                float v0 = sacc[t][c], v1 = sacc[t][c + 1];
                float h0f = __bfloat162float(__float2bfloat16(v0));
                float h1f = __bfloat162float(__float2bfloat16(v1));
                // q maps: 0->(t=2j,rows c0,c1)->a0 ; 1->(t=2j,c2,c3)->a1 ;
                //         2->(t=2j+1,c0,c1)->a2 ; 3->(t=2j+1,c2,c3)->a3
                ph[q] = pack_bf16x2(v0, v1);
                pl[q] = pack_bf16x2(v0 - h0f, v1 - h1f);
            }
#pragma unroll
            for (int nt = 0; nt < 4; nt++) {
                uint32_t vh[4], vl[4];
                uint32_t vaddr = smem_base + AV_H + (j * 16) * AROWB + nt * 32 + vrow_addr;
                ldmatrix_x4_trans(vh, vaddr);
                ldmatrix_x4_trans(vl, vaddr + (AV_L - AV_H));
                mma_bf16(oacc[2 * nt],     ph, vh + 0);
                mma_bf16(oacc[2 * nt + 1], ph, vh + 2);
                mma_bf16(oacc[2 * nt],     ph, vl + 0);
                mma_bf16(oacc[2 * nt + 1], ph, vl + 2);
                mma_bf16(oacc[2 * nt],     pl, vh + 0);
                mma_bf16(oacc[2 * nt + 1], pl, vh + 2);
            }
        }
    }

    // ---- normalize + write out ----
    const float inv0 = 1.f / lrow[0];
    const float inv1 = 1.f / lrow[1];
    const int row0 = q0 + wid * 16 + (lane >> 2);
#pragma unroll
    for (int t = 0; t < 8; t++) {
        const int col = h * DH + t * 8 + (lane & 3) * 2;
        float2 v0 = {oacc[t][0] * inv0, oacc[t][1] * inv0};
        float2 v1 = {oacc[t][2] * inv1, oacc[t][3] * inv1};
        *(float2*)(g_attn + (size_t)(b * 1024 + row0) * DM + col) = v0;
        *(float2*)(g_attn + (size_t)(b * 1024 + row0 + 8) * DM + col) = v1;
    }
}

// ---------------------------------------------------------------------------
extern "C" void kernel_launch(void* const* d_in, const int* in_sizes, int n_in,
                              void* d_out, int out_size)
{
    const float* q_in = (const float*)d_in[0];
    const float* k_in = (const float*)d_in[1];
    const float* v_in = (const float*)d_in[2];
    const float* Wq   = (const float*)d_in[3];
    const float* bq   = (const float*)d_in[4];
    const float* Wk   = (const float*)d_in[5];
    const float* bk   = (const float*)d_in[6];
    const float* Wv   = (const float*)d_in[7];
    const float* bv   = (const float*)d_in[8];
    const float* Wo   = (const float*)d_in[9];
    const float* bo   = (const float*)d_in[10];

    float *pQ, *pK, *pV, *pA;
    cudaGetSymbolAddress((void**)&pQ, g_Q);
    cudaGetSymbolAddress((void**)&pK, g_K);
    cudaGetSymbolAddress((void**)&pV, g_V);
    cudaGetSymbolAddress((void**)&pA, g_attn);
    __nv_bfloat16 *wqh, *wql, *wkh, *wkl, *wvh, *wvl, *woh, *wol;
    cudaGetSymbolAddress((void**)&wqh, g_wq_hi);
    cudaGetSymbolAddress((void**)&wql, g_wq_lo);
    cudaGetSymbolAddress((void**)&wkh, g_wk_hi);
    cudaGetSymbolAddress((void**)&wkl, g_wk_lo);
    cudaGetSymbolAddress((void**)&wvh, g_wv_hi);
    cudaGetSymbolAddress((void**)&wvl, g_wv_lo);
    cudaGetSymbolAddress((void**)&woh, g_wo_hi);
    cudaGetSymbolAddress((void**)&wol, g_wo_lo);

    cudaFuncSetAttribute(gemm_mma_kernel,
                         cudaFuncAttributeMaxDynamicSharedMemorySize, GEMM_SMEM);
    cudaFuncSetAttribute(attention_mma_kernel,
                         cudaFuncAttributeMaxDynamicSharedMemorySize, ATTN2_SMEM);

    dim3 tg(32, 32), tb(32, 8);
    transpose_w_kernel<<<tg, tb>>>(Wq, wqh, wql);
    transpose_w_kernel<<<tg, tb>>>(Wk, wkh, wkl);
    transpose_w_kernel<<<tg, tb>>>(Wv, wvh, wvl);
    transpose_w_kernel<<<tg, tb>>>(Wo, woh, wol);

    dim3 gg(DM / 128, MTOT / 128);   // (8, 32)
    gemm_mma_kernel<<<gg, 256, GEMM_SMEM>>>(q_in, wqh, wql, bq, pQ);
    gemm_mma_kernel<<<gg, 256, GEMM_SMEM>>>(k_in, wkh, wkl, bk, pK);
    gemm_mma_kernel<<<gg, 256, GEMM_SMEM>>>(v_in, wvh, wvl, bv, pV);

    attention_mma_kernel<<<dim3(8, 16, 4), 256, ATTN2_SMEM>>>();

    gemm_mma_kernel<<<gg, 256, GEMM_SMEM>>>(pA, woh, wol, bo, (float*)d_out);
}

// round 12
// speedup vs baseline: 2.4670x; 1.0617x over previous
#include <cuda_runtime.h>
#include <cuda_bf16.h>
#include <cstdint>
#include <math.h>

// ============================ problem constants ============================
#define MTOT 4096
#define DM   1024
#define NH   16
#define DH   64

// canonical intermediates: bf16 hi/lo pairs
__device__ __nv_bfloat16 g_q_hi[MTOT * DM], g_q_lo[MTOT * DM];
__device__ __nv_bfloat16 g_k_hi[MTOT * DM], g_k_lo[MTOT * DM];
__device__ __nv_bfloat16 g_v_hi[MTOT * DM], g_v_lo[MTOT * DM];
__device__ __nv_bfloat16 g_a_hi[MTOT * DM], g_a_lo[MTOT * DM];
// transposed split weights: [N=1024][K=1024] bf16
__device__ __nv_bfloat16 g_wq_hi[DM * DM], g_wq_lo[DM * DM];
__device__ __nv_bfloat16 g_wk_hi[DM * DM], g_wk_lo[DM * DM];
__device__ __nv_bfloat16 g_wv_hi[DM * DM], g_wv_lo[DM * DM];
__device__ __nv_bfloat16 g_wo_hi[DM * DM], g_wo_lo[DM * DM];

// ============================ PTX helpers (sm_80-class only) ============================
__device__ __forceinline__ uint32_t smem_to_u32(const void* p) {
    uint32_t a;
    asm("{ .reg .u64 t; cvta.to.shared.u64 t, %1; cvt.u32.u64 %0, t; }"
        : "=r"(a) : "l"(p));
    return a;
}
__device__ __forceinline__ void ldmatrix_x4(uint32_t* r, uint32_t addr) {
    asm volatile("ldmatrix.sync.aligned.m8n8.x4.shared.b16 {%0,%1,%2,%3}, [%4];"
                 : "=r"(r[0]), "=r"(r[1]), "=r"(r[2]), "=r"(r[3]) : "r"(addr));
}
__device__ __forceinline__ void ldmatrix_x4_trans(uint32_t* r, uint32_t addr) {
    asm volatile("ldmatrix.sync.aligned.m8n8.x4.trans.shared.b16 {%0,%1,%2,%3}, [%4];"
                 : "=r"(r[0]), "=r"(r[1]), "=r"(r[2]), "=r"(r[3]) : "r"(addr));
}
__device__ __forceinline__ void mma_bf16(float* c, const uint32_t* a, const uint32_t* b) {
    asm volatile(
        "mma.sync.aligned.m16n8k16.row.col.f32.bf16.bf16.f32 "
        "{%0,%1,%2,%3}, {%4,%5,%6,%7}, {%8,%9}, {%0,%1,%2,%3};"
        : "+f"(c[0]), "+f"(c[1]), "+f"(c[2]), "+f"(c[3])
        : "r"(a[0]), "r"(a[1]), "r"(a[2]), "r"(a[3]), "r"(b[0]), "r"(b[1]));
}
__device__ __forceinline__ void cp_async16(uint32_t saddr, const void* gaddr) {
    asm volatile("cp.async.ca.shared.global [%0], [%1], 16;"
                 :: "r"(saddr), "l"(gaddr) : "memory");
}
__device__ __forceinline__ void cp_async_commit() {
    asm volatile("cp.async.commit_group;" ::: "memory");
}
__device__ __forceinline__ void cp_async_wait0() {
    asm volatile("cp.async.wait_group 0;" ::: "memory");
}
__device__ __forceinline__ void cp_async_wait1() {
    asm volatile("cp.async.wait_group 1;" ::: "memory");
}
// pack (lo, hi) floats -> bf16x2 (second arg in upper 16 bits)
__device__ __forceinline__ uint32_t pack_bf16x2(float lo, float hi) {
    uint32_t r;
    asm("cvt.rn.bf16x2.f32 %0, %1, %2;" : "=r"(r) : "f"(hi), "f"(lo));
    return r;
}
__device__ __forceinline__ float bf16_rt(float x) {   // round-trip through bf16
    return __bfloat162float(__float2bfloat16(x));
}

// ---------------------------------------------------------------------------
// Weight transpose + bf16 split:  W[k][n] fp32  ->  T{hi,lo}[n][k] bf16
// ---------------------------------------------------------------------------
__global__ __launch_bounds__(256)
void transpose_w_kernel(const float* __restrict__ W,
                        __nv_bfloat16* __restrict__ Thi,
                        __nv_bfloat16* __restrict__ Tlo)
{
    __shared__ float t[32][33];
    const int n0 = blockIdx.x * 32, k0 = blockIdx.y * 32;
    const int tx = threadIdx.x, ty = threadIdx.y;   // 32 x 8
#pragma unroll
    for (int i = 0; i < 4; i++)
        t[ty + i * 8][tx] = W[(size_t)(k0 + ty + i * 8) * DM + n0 + tx];
    __syncthreads();
#pragma unroll
    for (int i = 0; i < 4; i++) {
        float x = t[tx][ty + i * 8];
        __nv_bfloat16 h = __float2bfloat16(x);
        __nv_bfloat16 l = __float2bfloat16(x - __bfloat162float(h));
        size_t o = (size_t)(n0 + ty + i * 8) * DM + k0 + tx;
        Thi[o] = h;
        Tlo[o] = l;
    }
}

// ---------------------------------------------------------------------------
// Shared GEMM tiling constants
// ---------------------------------------------------------------------------
#define ROWB 80
#define OFF_AH 0
#define OFF_AL 10240
#define OFF_BH 20480
#define OFF_BL 30720
#define STAGE_BYTES 40960
#define GEMM_SMEM (2 * STAGE_BYTES)

// ---------------------------------------------------------------------------
// GEMM variant 1 (QKV projections): fp32 A in (split in-kernel, proven path),
// OUTPUT = hi/lo bf16 pair (acc + bias split once here).
// ---------------------------------------------------------------------------
__global__ __launch_bounds__(256, 1)
void gemm_in32_out16(const float* __restrict__ A,
                     const __nv_bfloat16* __restrict__ Bhi,
                     const __nv_bfloat16* __restrict__ Blo,
                     const float* __restrict__ bias,
                     __nv_bfloat16* __restrict__ Chi,
                     __nv_bfloat16* __restrict__ Clo)
{
    extern __shared__ char smem[];
    const uint32_t smem_base = smem_to_u32(smem);
    const int tid  = threadIdx.x;
    const int wid  = tid >> 5;
    const int lane = tid & 31;
    const int wm   = wid >> 2;
    const int wn   = wid & 3;
    const int m0   = blockIdx.y * 128;
    const int n0   = blockIdx.x * 128;

    float acc[4][4][4];
#pragma unroll
    for (int i = 0; i < 4; i++)
#pragma unroll
        for (int j = 0; j < 4; j++)
#pragma unroll
            for (int k = 0; k < 4; k++) acc[i][j][k] = 0.f;

    {
        const uint32_t st = smem_base;
#pragma unroll
        for (int i = 0; i < 4; i++) {
            int idx = tid + i * 256;
            int r = idx >> 3, g = idx & 7;
            float4 v = *(const float4*)(A + (size_t)(m0 + r) * DM + g * 4);
            __nv_bfloat16 h0 = __float2bfloat16(v.x), h1 = __float2bfloat16(v.y);
            __nv_bfloat16 h2 = __float2bfloat16(v.z), h3 = __float2bfloat16(v.w);
            __nv_bfloat16 l0 = __float2bfloat16(v.x - __bfloat162float(h0));
            __nv_bfloat16 l1 = __float2bfloat16(v.y - __bfloat162float(h1));
            __nv_bfloat16 l2 = __float2bfloat16(v.z - __bfloat162float(h2));
            __nv_bfloat16 l3 = __float2bfloat16(v.w - __bfloat162float(h3));
            uint2 hv, lv;
            hv.x = ((uint32_t)__bfloat16_as_ushort(h1) << 16) | __bfloat16_as_ushort(h0);
            hv.y = ((uint32_t)__bfloat16_as_ushort(h3) << 16) | __bfloat16_as_ushort(h2);
            lv.x = ((uint32_t)__bfloat16_as_ushort(l1) << 16) | __bfloat16_as_ushort(l0);
            lv.y = ((uint32_t)__bfloat16_as_ushort(l3) << 16) | __bfloat16_as_ushort(l2);
            *(uint2*)(smem + OFF_AH + r * ROWB + g * 8) = hv;
            *(uint2*)(smem + OFF_AL + r * ROWB + g * 8) = lv;
        }
#pragma unroll
        for (int i = 0; i < 4; i++) {
            int idx = tid + i * 256;
            int half = idx >> 9;
            int j = idx & 511;
            int r = j >> 2, cgp = j & 3;
            const __nv_bfloat16* src = (half ? Blo : Bhi)
                + (size_t)(n0 + r) * DM + cgp * 8;
            cp_async16(st + OFF_BH + half * 10240 + r * ROWB + cgp * 16, src);
        }
        cp_async_commit();
    }

    for (int kc = 0; kc < 32; kc++) {
        const int s = kc & 1;
        const uint32_t st = smem_base + s * STAGE_BYTES;

        float4 av[4];
        if (kc < 31) {
#pragma unroll
            for (int i = 0; i < 4; i++) {
                int idx = tid + i * 256;
                int r = idx >> 3, g = idx & 7;
                av[i] = *(const float4*)(A + (size_t)(m0 + r) * DM
                                         + (kc + 1) * 32 + g * 4);
            }
        }

        cp_async_wait0();
        __syncthreads();

        if (kc < 31) {
            const uint32_t stn = smem_base + ((kc + 1) & 1) * STAGE_BYTES;
#pragma unroll
            for (int i = 0; i < 4; i++) {
                int idx = tid + i * 256;
                int half = idx >> 9;
                int j = idx & 511;
                int r = j >> 2, cgp = j & 3;
                const __nv_bfloat16* src = (half ? Blo : Bhi)
                    + (size_t)(n0 + r) * DM + (kc + 1) * 32 + cgp * 8;
                cp_async16(stn + OFF_BH + half * 10240 + r * ROWB + cgp * 16, src);
            }
            cp_async_commit();
        }

        const int arow  = wm * 64 + (lane & 15);
        const int acolb0 = (lane >> 4) * 16;
        const int bg    = lane >> 3;
        const int brow  = wn * 32 + ((bg & 2) ? 8 : 0) + (lane & 7);
        const int bcolb0 = (bg & 1) * 16;
#pragma unroll
        for (int ks = 0; ks < 2; ks++) {
            const int acolb = ks * 32 + acolb0;
            const int bcolb = ks * 32 + bcolb0;
            uint32_t ah[4][4], alr[4][4], bhf[4][2], blf[4][2];
#pragma unroll
            for (int mi = 0; mi < 4; mi++)
                ldmatrix_x4(ah[mi], st + OFF_AH + (arow + mi * 16) * ROWB + acolb);
#pragma unroll
            for (int p = 0; p < 2; p++) {
                uint32_t r4[4];
                ldmatrix_x4(r4, st + OFF_BH + (brow + p * 16) * ROWB + bcolb);
                bhf[p * 2][0] = r4[0]; bhf[p * 2][1] = r4[1];
                bhf[p * 2 + 1][0] = r4[2]; bhf[p * 2 + 1][1] = r4[3];
            }
#pragma unroll
            for (int mi = 0; mi < 4; mi++)
#pragma unroll
                for (int ni = 0; ni < 4; ni++)
                    mma_bf16(acc[mi][ni], ah[mi], bhf[ni]);
#pragma unroll
            for (int mi = 0; mi < 4; mi++)
                ldmatrix_x4(alr[mi], st + OFF_AL + (arow + mi * 16) * ROWB + acolb);
#pragma unroll
            for (int mi = 0; mi < 4; mi++)
#pragma unroll
                for (int ni = 0; ni < 4; ni++)
                    mma_bf16(acc[mi][ni], alr[mi], bhf[ni]);
#pragma unroll
            for (int p = 0; p < 2; p++) {
                uint32_t r4[4];
                ldmatrix_x4(r4, st + OFF_BL + (brow + p * 16) * ROWB + bcolb);
                blf[p * 2][0] = r4[0]; blf[p * 2][1] = r4[1];
                blf[p * 2 + 1][0] = r4[2]; blf[p * 2 + 1][1] = r4[3];
            }
#pragma unroll
            for (int mi = 0; mi < 4; mi++)
#pragma unroll
                for (int ni = 0; ni < 4; ni++)
                    mma_bf16(acc[mi][ni], ah[mi], blf[ni]);
        }

        if (kc < 31) {
            char* stn = smem + ((kc + 1) & 1) * STAGE_BYTES;
#pragma unroll
            for (int i = 0; i < 4; i++) {
                int idx = tid + i * 256;
                int r = idx >> 3, g = idx & 7;
                float4 v = av[i];
                __nv_bfloat16 h0 = __float2bfloat16(v.x), h1 = __float2bfloat16(v.y);
                __nv_bfloat16 h2 = __float2bfloat16(v.z), h3 = __float2bfloat16(v.w);
                __nv_bfloat16 l0 = __float2bfloat16(v.x - __bfloat162float(h0));
                __nv_bfloat16 l1 = __float2bfloat16(v.y - __bfloat162float(h1));
                __nv_bfloat16 l2 = __float2bfloat16(v.z - __bfloat162float(h2));
                __nv_bfloat16 l3 = __float2bfloat16(v.w - __bfloat162float(h3));
                uint2 hv, lv;
                hv.x = ((uint32_t)__bfloat16_as_ushort(h1) << 16) | __bfloat16_as_ushort(h0);
                hv.y = ((uint32_t)__bfloat16_as_ushort(h3) << 16) | __bfloat16_as_ushort(h2);
                lv.x = ((uint32_t)__bfloat16_as_ushort(l1) << 16) | __bfloat16_as_ushort(l0);
                lv.y = ((uint32_t)__bfloat16_as_ushort(l3) << 16) | __bfloat16_as_ushort(l2);
                *(uint2*)(stn + OFF_AH + r * ROWB + g * 8) = hv;
                *(uint2*)(stn + OFF_AL + r * ROWB + g * 8) = lv;
            }
        }
    }

    // ---- epilogue: acc + bias -> hi/lo bf16 ----
#pragma unroll
    for (int mi = 0; mi < 4; mi++) {
        const int r0 = m0 + wm * 64 + mi * 16 + (lane >> 2);
#pragma unroll
        for (int ni = 0; ni < 4; ni++) {
            const int col = n0 + wn * 32 + ni * 8 + (lane & 3) * 2;
            const float b0 = bias[col], b1 = bias[col + 1];
            float x0 = acc[mi][ni][0] + b0, x1 = acc[mi][ni][1] + b1;
            float x2 = acc[mi][ni][2] + b0, x3 = acc[mi][ni][3] + b1;
            *(uint32_t*)&Chi[(size_t)r0 * DM + col] = pack_bf16x2(x0, x1);
            *(uint32_t*)&Clo[(size_t)r0 * DM + col] =
                pack_bf16x2(x0 - bf16_rt(x0), x1 - bf16_rt(x1));
            *(uint32_t*)&Chi[(size_t)(r0 + 8) * DM + col] = pack_bf16x2(x2, x3);
            *(uint32_t*)&Clo[(size_t)(r0 + 8) * DM + col] =
                pack_bf16x2(x2 - bf16_rt(x2), x3 - bf16_rt(x3));
        }
    }
}

// ---------------------------------------------------------------------------
// GEMM variant 2 (output projection): pre-split bf16 A in via cp.async,
// fp32 C out + bias. Full cp.async 2-stage pipeline on both operands.
// ---------------------------------------------------------------------------
__global__ __launch_bounds__(256, 1)
void gemm_in16_out32(const __nv_bfloat16* __restrict__ Ahi,
                     const __nv_bfloat16* __restrict__ Alo,
                     const __nv_bfloat16* __restrict__ Bhi,
                     const __nv_bfloat16* __restrict__ Blo,
                     const float* __restrict__ bias,
                     float* __restrict__ C)
{
    extern __shared__ char smem[];
    const uint32_t smem_base = smem_to_u32(smem);
    const int tid  = threadIdx.x;
    const int wid  = tid >> 5;
    const int lane = tid & 31;
    const int wm   = wid >> 2;
    const int wn   = wid & 3;
    const int m0   = blockIdx.y * 128;
    const int n0   = blockIdx.x * 128;

    float acc[4][4][4];
#pragma unroll
    for (int i = 0; i < 4; i++)
#pragma unroll
        for (int j = 0; j < 4; j++)
#pragma unroll
            for (int k = 0; k < 4; k++) acc[i][j][k] = 0.f;

    // prologue: chunk 0 into stage 0
    {
        const uint32_t st = smem_base;
#pragma unroll
        for (int i = 0; i < 4; i++) {
            int idx = tid + i * 256;
            int half = idx >> 9, j = idx & 511;
            int r = j >> 2, p = j & 3;
            const __nv_bfloat16* src = (half ? Alo : Ahi) + (size_t)(m0 + r) * DM + p * 8;
            cp_async16(st + (half ? OFF_AL : OFF_AH) + r * ROWB + p * 16, src);
        }
#pragma unroll
        for (int i = 0; i < 4; i++) {
            int idx = tid + i * 256;
            int half = idx >> 9, j = idx & 511;
            int r = j >> 2, p = j & 3;
            const __nv_bfloat16* src = (half ? Blo : Bhi) + (size_t)(n0 + r) * DM + p * 8;
            cp_async16(st + OFF_BH + half * 10240 + r * ROWB + p * 16, src);
        }
        cp_async_commit();
    }

    for (int kc = 0; kc < 32; kc++) {
        const uint32_t st = smem_base + (kc & 1) * STAGE_BYTES;

        if (kc < 31) {
            const uint32_t stn = smem_base + ((kc + 1) & 1) * STAGE_BYTES;
#pragma unroll
            for (int i = 0; i < 4; i++) {
                int idx = tid + i * 256;
                int half = idx >> 9, j = idx & 511;
                int r = j >> 2, p = j & 3;
                const __nv_bfloat16* src = (half ? Alo : Ahi)
                    + (size_t)(m0 + r) * DM + (kc + 1) * 32 + p * 8;
                cp_async16(stn + (half ? OFF_AL : OFF_AH) + r * ROWB + p * 16, src);
            }
#pragma unroll
            for (int i = 0; i < 4; i++) {
                int idx = tid + i * 256;
                int half = idx >> 9, j = idx & 511;
                int r = j >> 2, p = j & 3;
                const __nv_bfloat16* src = (half ? Blo : Bhi)
                    + (size_t)(n0 + r) * DM + (kc + 1) * 32 + p * 8;
                cp_async16(stn + OFF_BH + half * 10240 + r * ROWB + p * 16, src);
            }
            cp_async_commit();
            cp_async_wait1();
        } else {
            cp_async_wait0();
        }
        __syncthreads();

        const int arow  = wm * 64 + (lane & 15);
        const int acolb0 = (lane >> 4) * 16;
        const int bg    = lane >> 3;
        const int brow  = wn * 32 + ((bg & 2) ? 8 : 0) + (lane & 7);
        const int bcolb0 = (bg & 1) * 16;
#pragma unroll
        for (int ks = 0; ks < 2; ks++) {
            const int acolb = ks * 32 + acolb0;
            const int bcolb = ks * 32 + bcolb0;
            uint32_t ah[4][4], alr[4][4], bhf[4][2], blf[4][2];
#pragma unroll
            for (int mi = 0; mi < 4; mi++)
                ldmatrix_x4(ah[mi], st + OFF_AH + (arow + mi * 16) * ROWB + acolb);
#pragma unroll
            for (int p = 0; p < 2; p++) {
                uint32_t r4[4];
                ldmatrix_x4(r4, st + OFF_BH + (brow + p * 16) * ROWB + bcolb);
                bhf[p * 2][0] = r4[0]; bhf[p * 2][1] = r4[1];
                bhf[p * 2 + 1][0] = r4[2]; bhf[p * 2 + 1][1] = r4[3];
            }
#pragma unroll
            for (int mi = 0; mi < 4; mi++)
#pragma unroll
                for (int ni = 0; ni < 4; ni++)
                    mma_bf16(acc[mi][ni], ah[mi], bhf[ni]);
#pragma unroll
            for (int mi = 0; mi < 4; mi++)
                ldmatrix_x4(alr[mi], st + OFF_AL + (arow + mi * 16) * ROWB + acolb);
#pragma unroll
            for (int mi = 0; mi < 4; mi++)
#pragma unroll
                for (int ni = 0; ni < 4; ni++)
                    mma_bf16(acc[mi][ni], alr[mi], bhf[ni]);
#pragma unroll
            for (int p = 0; p < 2; p++) {
                uint32_t r4[4];
                ldmatrix_x4(r4, st + OFF_BL + (brow + p * 16) * ROWB + bcolb);
                blf[p * 2][0] = r4[0]; blf[p * 2][1] = r4[1];
                blf[p * 2 + 1][0] = r4[2]; blf[p * 2 + 1][1] = r4[3];
            }
#pragma unroll
            for (int mi = 0; mi < 4; mi++)
#pragma unroll
                for (int ni = 0; ni < 4; ni++)
                    mma_bf16(acc[mi][ni], ah[mi], blf[ni]);
        }
        __syncthreads();   // protect stage before next-iter cp.async overwrites
    }

#pragma unroll
    for (int mi = 0; mi < 4; mi++) {
        const int r0 = m0 + wm * 64 + mi * 16 + (lane >> 2);
#pragma unroll
        for (int ni = 0; ni < 4; ni++) {
            const int col = n0 + wn * 32 + ni * 8 + (lane & 3) * 2;
            const float b0 = bias[col], b1 = bias[col + 1];
            float2 v0 = {acc[mi][ni][0] + b0, acc[mi][ni][1] + b1};
            float2 v1 = {acc[mi][ni][2] + b0, acc[mi][ni][3] + b1};
            *(float2*)(C + (size_t)r0 * DM + col) = v0;
            *(float2*)(C + (size_t)(r0 + 8) * DM + col) = v1;
        }
    }
}

// ---------------------------------------------------------------------------
// Flash attention v3 — HMMA split-bf16, all inputs pre-split, cp.async
// double-buffered K/V, zero conversion ALU in the mainloop.
// Output written as hi/lo bf16 for the final GEMM.
// ---------------------------------------------------------------------------
#define AROWB 144
#define AQ_H 0
#define AQ_L (128 * AROWB)                  // 18432
#define AST0 (2 * 128 * AROWB)              // 36864
#define TILE_B (64 * AROWB)                 // 9216
#define ATTN3_SMEM (AST0 + 2 * 4 * TILE_B)  // 110592

__global__ __launch_bounds__(256)
void attention_mma3_kernel(const __nv_bfloat16* __restrict__ Qh_,
                           const __nv_bfloat16* __restrict__ Ql_,
                           const __nv_bfloat16* __restrict__ Kh_,
                           const __nv_bfloat16* __restrict__ Kl_,
                           const __nv_bfloat16* __restrict__ Vh_,
                           const __nv_bfloat16* __restrict__ Vl_,
                           __nv_bfloat16* __restrict__ Ah_,
                           __nv_bfloat16* __restrict__ Al_)
{
    extern __shared__ char smem[];
    const uint32_t smem_base = smem_to_u32(smem);
    const int tid  = threadIdx.x;
    const int wid  = tid >> 5;
    const int lane = tid & 31;
    const int b    = blockIdx.z;
    const int h    = blockIdx.y;
    const int q0   = blockIdx.x * 128;

    const size_t tok0 = (size_t)b * 1024;
    const int colbase = h * DH;

    // ---- prologue: stage Q (once) + K/V tile 0, one commit group ----
    {
#pragma unroll
        for (int i = 0; i < 8; i++) {
            int idx = tid + i * 256;            // 2048 16B-pieces
            int half = idx >> 10, j = idx & 1023;
            int r = j >> 3, p = j & 7;
            const __nv_bfloat16* src = (half ? Ql_ : Qh_)
                + (tok0 + q0 + r) * DM + colbase + p * 8;
            cp_async16(smem_base + (half ? AQ_L : AQ_H) + r * AROWB + p * 16, src);
        }
        const __nv_bfloat16* srcs[4] = {
            Kh_ + tok0 * DM + colbase, Kl_ + tok0 * DM + colbase,
            Vh_ + tok0 * DM + colbase, Vl_ + tok0 * DM + colbase };
#pragma unroll
        for (int i = 0; i < 8; i++) {
            int idx = tid + i * 256;            // 2048 16B-pieces
            int t4 = idx >> 9, j = idx & 511;
            int r = j >> 3, p = j & 7;
            cp_async16(smem_base + AST0 + t4 * TILE_B + r * AROWB + p * 16,
                       srcs[t4] + (size_t)r * DM + p * 8);
        }
        cp_async_commit();
    }

    float oacc[8][4];
    float mrow[2], lrow[2];
#pragma unroll
    for (int t = 0; t < 8; t++)
#pragma unroll
        for (int c = 0; c < 4; c++) oacc[t][c] = 0.f;
    mrow[0] = mrow[1] = -1e30f;
    lrow[0] = lrow[1] = 0.f;

    const uint32_t aH = smem_base + AQ_H + (wid * 16 + (lane & 15)) * AROWB + (lane >> 4) * 16;
    const uint32_t aL = smem_base + AQ_L + (wid * 16 + (lane & 15)) * AROWB + (lane >> 4) * 16;
    const int bg = lane >> 3;
    const int brow_off = ((bg & 2) ? 8 : 0) + (lane & 7);
    const int bcolb = (bg & 1) * 16;
    const uint32_t vrow_addr = (lane & 15) * AROWB + (lane >> 4) * 16;

    for (int kt = 0; kt < 16; kt++) {
        const uint32_t stg = smem_base + AST0 + (kt & 1) * (4 * TILE_B);

        // issue next tile into the other stage (computed 2 iters ago; safe
        // via end-of-iter barrier), then drain so current stage is ready
        if (kt < 15) {
            const uint32_t stgn = smem_base + AST0 + ((kt + 1) & 1) * (4 * TILE_B);
            const size_t t0 = tok0 + (size_t)(kt + 1) * 64;
            const __nv_bfloat16* srcs[4] = {
                Kh_ + t0 * DM + colbase, Kl_ + t0 * DM + colbase,
                Vh_ + t0 * DM + colbase, Vl_ + t0 * DM + colbase };
#pragma unroll
            for (int i = 0; i < 8; i++) {
                int idx = tid + i * 256;
                int t4 = idx >> 9, j = idx & 511;
                int r = j >> 3, p = j & 7;
                cp_async16(stgn + t4 * TILE_B + r * AROWB + p * 16,
                           srcs[t4] + (size_t)r * DM + p * 8);
            }
            cp_async_commit();
            cp_async_wait1();
        } else {
            cp_async_wait0();
        }
        __syncthreads();

        // ---- S = Q K^T (split x3) ----
        float sacc[8][4];
#pragma unroll
        for (int t = 0; t < 8; t++)
#pragma unroll
            for (int c = 0; c < 4; c++) sacc[t][c] = 0.f;

#pragma unroll
        for (int ks = 0; ks < 4; ks++) {
            uint32_t qh[4], ql[4];
            ldmatrix_x4(qh, aH + ks * 32);
            ldmatrix_x4(ql, aL + ks * 32);
#pragma unroll
            for (int nt = 0; nt < 4; nt++) {
                uint32_t kh[4], kl[4];
                uint32_t baddr = stg + (nt * 16 + brow_off) * AROWB + ks * 32 + bcolb;
                ldmatrix_x4(kh, baddr);
                ldmatrix_x4(kl, baddr + TILE_B);
                mma_bf16(sacc[2 * nt],     qh, kh + 0);
                mma_bf16(sacc[2 * nt + 1], qh, kh + 2);
                mma_bf16(sacc[2 * nt],     qh, kl + 0);
                mma_bf16(sacc[2 * nt + 1], qh, kl + 2);
                mma_bf16(sacc[2 * nt],     ql, kh + 0);
                mma_bf16(sacc[2 * nt + 1], ql, kh + 2);
            }
        }

        // ---- online softmax ----
#pragma unroll
        for (int half = 0; half < 2; half++) {
            const int c0 = half * 2;
            float rm = -1e30f;
#pragma unroll
            for (int t = 0; t < 8; t++) {
                sacc[t][c0]     *= 0.125f;
                sacc[t][c0 + 1] *= 0.125f;
                rm = fmaxf(rm, fmaxf(sacc[t][c0], sacc[t][c0 + 1]));
            }
            rm = fmaxf(rm, __shfl_xor_sync(0xffffffffu, rm, 1));
            rm = fmaxf(rm, __shfl_xor_sync(0xffffffffu, rm, 2));
            float mnew = fmaxf(mrow[half], rm);
            float corr = __expf(mrow[half] - mnew);
            mrow[half] = mnew;
            float rs = 0.f;
#pragma unroll
            for (int t = 0; t < 8; t++) {
                float p0 = __expf(sacc[t][c0] - mnew);
                float p1 = __expf(sacc[t][c0 + 1] - mnew);
                sacc[t][c0] = p0;
                sacc[t][c0 + 1] = p1;
                rs += p0 + p1;
            }
            rs += __shfl_xor_sync(0xffffffffu, rs, 1);
            rs += __shfl_xor_sync(0xffffffffu, rs, 2);
            lrow[half] = lrow[half] * corr + rs;
#pragma unroll
            for (int t = 0; t < 8; t++) {
                oacc[t][c0]     *= corr;
                oacc[t][c0 + 1] *= corr;
            }
        }

        // ---- O += P V (split x3) ----
#pragma unroll
        for (int j = 0; j < 4; j++) {
            uint32_t ph[4], pl[4];
#pragma unroll
            for (int q = 0; q < 4; q++) {
                const int t = 2 * j + (q >> 1);
                const int c = (q & 1) * 2;
                float v0 = sacc[t][c], v1 = sacc[t][c + 1];
                ph[q] = pack_bf16x2(v0, v1);
                pl[q] = pack_bf16x2(v0 - bf16_rt(v0), v1 - bf16_rt(v1));
            }
#pragma unroll
            for (int nt = 0; nt < 4; nt++) {
                uint32_t vh[4], vl[4];
                uint32_t vaddr = stg + 2 * TILE_B + (j * 16) * AROWB + nt * 32 + vrow_addr;
                ldmatrix_x4_trans(vh, vaddr);
                ldmatrix_x4_trans(vl, vaddr + TILE_B);
                mma_bf16(oacc[2 * nt],     ph, vh + 0);
                mma_bf16(oacc[2 * nt + 1], ph, vh + 2);
                mma_bf16(oacc[2 * nt],     ph, vl + 0);
                mma_bf16(oacc[2 * nt + 1], ph, vl + 2);
                mma_bf16(oacc[2 * nt],     pl, vh + 0);
                mma_bf16(oacc[2 * nt + 1], pl, vh + 2);
            }
        }
        __syncthreads();   // all warps done reading this stage
    }

    // ---- normalize + split-write attn (hi/lo bf16) ----
    const float inv0 = 1.f / lrow[0];
    const float inv1 = 1.f / lrow[1];
    const int row0 = q0 + wid * 16 + (lane >> 2);
#pragma unroll
    for (int t = 0; t < 8; t++) {
        const int col = colbase + t * 8 + (lane & 3) * 2;
        float x0 = oacc[t][0] * inv0, x1 = oacc[t][1] * inv0;
        float x2 = oacc[t][2] * inv1, x3 = oacc[t][3] * inv1;
        *(uint32_t*)&Ah_[(tok0 + row0) * DM + col] = pack_bf16x2(x0, x1);
        *(uint32_t*)&Al_[(tok0 + row0) * DM + col] =
            pack_bf16x2(x0 - bf16_rt(x0), x1 - bf16_rt(x1));
        *(uint32_t*)&Ah_[(tok0 + row0 + 8) * DM + col] = pack_bf16x2(x2, x3);
        *(uint32_t*)&Al_[(tok0 + row0 + 8) * DM + col] =
            pack_bf16x2(x2 - bf16_rt(x2), x3 - bf16_rt(x3));
    }
}

// ---------------------------------------------------------------------------
extern "C" void kernel_launch(void* const* d_in, const int* in_sizes, int n_in,
                              void* d_out, int out_size)
{
    const float* q_in = (const float*)d_in[0];
    const float* k_in = (const float*)d_in[1];
    const float* v_in = (const float*)d_in[2];
    const float* Wq   = (const float*)d_in[3];
    const float* bq   = (const float*)d_in[4];
    const float* Wk   = (const float*)d_in[5];
    const float* bk   = (const float*)d_in[6];
    const float* Wv   = (const float*)d_in[7];
    const float* bv   = (const float*)d_in[8];
    const float* Wo   = (const float*)d_in[9];
    const float* bo   = (const float*)d_in[10];

    __nv_bfloat16 *pqh, *pql, *pkh, *pkl, *pvh, *pvl, *pah, *pal;
    cudaGetSymbolAddress((void**)&pqh, g_q_hi);
    cudaGetSymbolAddress((void**)&pql, g_q_lo);
    cudaGetSymbolAddress((void**)&pkh, g_k_hi);
    cudaGetSymbolAddress((void**)&pkl, g_k_lo);
    cudaGetSymbolAddress((void**)&pvh, g_v_hi);
    cudaGetSymbolAddress((void**)&pvl, g_v_lo);
    cudaGetSymbolAddress((void**)&pah, g_a_hi);
    cudaGetSymbolAddress((void**)&pal, g_a_lo);
    __nv_bfloat16 *wqh, *wql, *wkh, *wkl, *wvh, *wvl, *woh, *wol;
    cudaGetSymbolAddress((void**)&wqh, g_wq_hi);
    cudaGetSymbolAddress((void**)&wql, g_wq_lo);
    cudaGetSymbolAddress((void**)&wkh, g_wk_hi);
    cudaGetSymbolAddress((void**)&wkl, g_wk_lo);
    cudaGetSymbolAddress((void**)&wvh, g_wv_hi);
    cudaGetSymbolAddress((void**)&wvl, g_wv_lo);
    cudaGetSymbolAddress((void**)&woh, g_wo_hi);
    cudaGetSymbolAddress((void**)&wol, g_wo_lo);

    cudaFuncSetAttribute(gemm_in32_out16,
                         cudaFuncAttributeMaxDynamicSharedMemorySize, GEMM_SMEM);
    cudaFuncSetAttribute(gemm_in16_out32,
                         cudaFuncAttributeMaxDynamicSharedMemorySize, GEMM_SMEM);
    cudaFuncSetAttribute(attention_mma3_kernel,
                         cudaFuncAttributeMaxDynamicSharedMemorySize, ATTN3_SMEM);

    dim3 tg(32, 32), tb(32, 8);
    transpose_w_kernel<<<tg, tb>>>(Wq, wqh, wql);
    transpose_w_kernel<<<tg, tb>>>(Wk, wkh, wkl);
    transpose_w_kernel<<<tg, tb>>>(Wv, wvh, wvl);
    transpose_w_kernel<<<tg, tb>>>(Wo, woh, wol);

    dim3 gg(DM / 128, MTOT / 128);   // (8, 32)
    gemm_in32_out16<<<gg, 256, GEMM_SMEM>>>(q_in, wqh, wql, bq, pqh, pql);
    gemm_in32_out16<<<gg, 256, GEMM_SMEM>>>(k_in, wkh, wkl, bk, pkh, pkl);
    gemm_in32_out16<<<gg, 256, GEMM_SMEM>>>(v_in, wvh, wvl, bv, pvh, pvl);

    attention_mma3_kernel<<<dim3(8, 16, 4), 256, ATTN3_SMEM>>>(
        pqh, pql, pkh, pkl, pvh, pvl, pah, pal);

    gemm_in16_out32<<<gg, 256, GEMM_SMEM>>>(pah, pal, woh, wol, bo, (float*)d_out);
}

// round 13
// speedup vs baseline: 4.1958x; 1.7008x over previous
#include <cuda_runtime.h>
#include <cuda_fp16.h>
#include <cstdint>
#include <math.h>

// ============================ problem constants ============================
#define MTOT 4096
#define DM   1024
#define NH   16
#define DH   64

// canonical intermediates: single fp16
__device__ __half g_q16[MTOT * DM];
__device__ __half g_k16[MTOT * DM];
__device__ __half g_v16[MTOT * DM];
__device__ __half g_a16[MTOT * DM];
// transposed split weights: [N=1024][K=1024] fp16 hi/lo
__device__ __half g_wq_hi[DM * DM], g_wq_lo[DM * DM];
__device__ __half g_wk_hi[DM * DM], g_wk_lo[DM * DM];
__device__ __half g_wv_hi[DM * DM], g_wv_lo[DM * DM];
__device__ __half g_wo_hi[DM * DM], g_wo_lo[DM * DM];

// ============================ PTX helpers ============================
__device__ __forceinline__ uint32_t smem_to_u32(const void* p) {
    uint32_t a;
    asm("{ .reg .u64 t; cvta.to.shared.u64 t, %1; cvt.u32.u64 %0, t; }"
        : "=r"(a) : "l"(p));
    return a;
}
__device__ __forceinline__ void ldmatrix_x4(uint32_t* r, uint32_t addr) {
    asm volatile("ldmatrix.sync.aligned.m8n8.x4.shared.b16 {%0,%1,%2,%3}, [%4];"
                 : "=r"(r[0]), "=r"(r[1]), "=r"(r[2]), "=r"(r[3]) : "r"(addr));
}
__device__ __forceinline__ void ldmatrix_x4_trans(uint32_t* r, uint32_t addr) {
    asm volatile("ldmatrix.sync.aligned.m8n8.x4.trans.shared.b16 {%0,%1,%2,%3}, [%4];"
                 : "=r"(r[0]), "=r"(r[1]), "=r"(r[2]), "=r"(r[3]) : "r"(addr));
}
__device__ __forceinline__ void mma_f16(float* c, const uint32_t* a, const uint32_t* b) {
    asm volatile(
        "mma.sync.aligned.m16n8k16.row.col.f32.f16.f16.f32 "
        "{%0,%1,%2,%3}, {%4,%5,%6,%7}, {%8,%9}, {%0,%1,%2,%3};"
        : "+f"(c[0]), "+f"(c[1]), "+f"(c[2]), "+f"(c[3])
        : "r"(a[0]), "r"(a[1]), "r"(a[2]), "r"(a[3]), "r"(b[0]), "r"(b[1]));
}
__device__ __forceinline__ void cp_async16(uint32_t saddr, const void* gaddr) {
    asm volatile("cp.async.ca.shared.global [%0], [%1], 16;"
                 :: "r"(saddr), "l"(gaddr) : "memory");
}
__device__ __forceinline__ void cp_async_commit() {
    asm volatile("cp.async.commit_group;" ::: "memory");
}
__device__ __forceinline__ void cp_async_wait0() {
    asm volatile("cp.async.wait_group 0;" ::: "memory");
}
__device__ __forceinline__ void cp_async_wait1() {
    asm volatile("cp.async.wait_group 1;" ::: "memory");
}
// pack (lo, hi) floats -> f16x2 (second arg in upper 16 bits)
__device__ __forceinline__ uint32_t pack_f16x2(float lo, float hi) {
    uint32_t r;
    asm("cvt.rn.f16x2.f32 %0, %1, %2;" : "=r"(r) : "f"(hi), "f"(lo));
    return r;
}

// ---------------------------------------------------------------------------
// Weight transpose + fp16 split:  W[k][n] fp32  ->  T{hi,lo}[n][k] fp16
// ---------------------------------------------------------------------------
__global__ __launch_bounds__(256)
void transpose_w_kernel(const float* __restrict__ W,
                        __half* __restrict__ Thi,
                        __half* __restrict__ Tlo)
{
    __shared__ float t[32][33];
    const int n0 = blockIdx.x * 32, k0 = blockIdx.y * 32;
    const int tx = threadIdx.x, ty = threadIdx.y;   // 32 x 8
#pragma unroll
    for (int i = 0; i < 4; i++)
        t[ty + i * 8][tx] = W[(size_t)(k0 + ty + i * 8) * DM + n0 + tx];
    __syncthreads();
#pragma unroll
    for (int i = 0; i < 4; i++) {
        float x = t[tx][ty + i * 8];
        __half h = __float2half(x);
        __half l = __float2half(x - __half2float(h));
        size_t o = (size_t)(n0 + ty + i * 8) * DM + k0 + tx;
        Thi[o] = h;
        Tlo[o] = l;
    }
}

// ---------------------------------------------------------------------------
// Shared GEMM tiling constants (A single fp16, B hi/lo fp16)
// ---------------------------------------------------------------------------
#define ROWB 80
#define OFF_A  0
#define OFF_BH 10240
#define OFF_BL 20480
#define STAGE_BYTES 30720
#define GEMM_SMEM (2 * STAGE_BYTES)   // 61440

// ---------------------------------------------------------------------------
// GEMM variant 1 (QKV projections): fp32 A in -> single fp16 smem,
// B = pre-split hi/lo, 2 MMA terms; output single fp16 (+bias).
// ---------------------------------------------------------------------------
__global__ __launch_bounds__(256, 1)
void gemm_in32_out16(const float* __restrict__ A,
                     const __half* __restrict__ Bhi,
                     const __half* __restrict__ Blo,
                     const float* __restrict__ bias,
                     __half* __restrict__ C16)
{
    extern __shared__ char smem[];
    const uint32_t smem_base = smem_to_u32(smem);
    const int tid  = threadIdx.x;
    const int wid  = tid >> 5;
    const int lane = tid & 31;
    const int wm   = wid >> 2;
    const int wn   = wid & 3;
    const int m0   = blockIdx.y * 128;
    const int n0   = blockIdx.x * 128;

    float acc[4][4][4];
#pragma unroll
    for (int i = 0; i < 4; i++)
#pragma unroll
        for (int j = 0; j < 4; j++)
#pragma unroll
            for (int k = 0; k < 4; k++) acc[i][j][k] = 0.f;

    // ---- prologue: chunk 0 ----
    {
        const uint32_t st = smem_base;
#pragma unroll
        for (int i = 0; i < 4; i++) {
            int idx = tid + i * 256;
            int r = idx >> 3, g = idx & 7;
            float4 v = *(const float4*)(A + (size_t)(m0 + r) * DM + g * 4);
            uint2 hv;
            hv.x = pack_f16x2(v.x, v.y);
            hv.y = pack_f16x2(v.z, v.w);
            *(uint2*)(smem + OFF_A + r * ROWB + g * 8) = hv;
        }
#pragma unroll
        for (int i = 0; i < 4; i++) {
            int idx = tid + i * 256;
            int half_ = idx >> 9;
            int j = idx & 511;
            int r = j >> 2, p = j & 3;
            const __half* src = (half_ ? Blo : Bhi) + (size_t)(n0 + r) * DM + p * 8;
            cp_async16(st + OFF_BH + half_ * 10240 + r * ROWB + p * 16, src);
        }
        cp_async_commit();
    }

    for (int kc = 0; kc < 32; kc++) {
        const uint32_t st = smem_base + (kc & 1) * STAGE_BYTES;

        float4 av[4];
        if (kc < 31) {
#pragma unroll
            for (int i = 0; i < 4; i++) {
                int idx = tid + i * 256;
                int r = idx >> 3, g = idx & 7;
                av[i] = *(const float4*)(A + (size_t)(m0 + r) * DM
                                         + (kc + 1) * 32 + g * 4);
            }
        }

        cp_async_wait0();
        __syncthreads();

        if (kc < 31) {
            const uint32_t stn = smem_base + ((kc + 1) & 1) * STAGE_BYTES;
#pragma unroll
            for (int i = 0; i < 4; i++) {
                int idx = tid + i * 256;
                int half_ = idx >> 9;
                int j = idx & 511;
                int r = j >> 2, p = j & 3;
                const __half* src = (half_ ? Blo : Bhi)
                    + (size_t)(n0 + r) * DM + (kc + 1) * 32 + p * 8;
                cp_async16(stn + OFF_BH + half_ * 10240 + r * ROWB + p * 16, src);
            }
            cp_async_commit();
        }

        const int arow  = wm * 64 + (lane & 15);
        const int acolb0 = (lane >> 4) * 16;
        const int bg    = lane >> 3;
        const int brow  = wn * 32 + ((bg & 2) ? 8 : 0) + (lane & 7);
        const int bcolb0 = (bg & 1) * 16;
#pragma unroll
        for (int ks = 0; ks < 2; ks++) {
            const int acolb = ks * 32 + acolb0;
            const int bcolb = ks * 32 + bcolb0;
            uint32_t ah[4][4], bhf[4][2], blf[4][2];
#pragma unroll
            for (int mi = 0; mi < 4; mi++)
                ldmatrix_x4(ah[mi], st + OFF_A + (arow + mi * 16) * ROWB + acolb);
#pragma unroll
            for (int p = 0; p < 2; p++) {
                uint32_t r4[4];
                ldmatrix_x4(r4, st + OFF_BH + (brow + p * 16) * ROWB + bcolb);
                bhf[p * 2][0] = r4[0]; bhf[p * 2][1] = r4[1];
                bhf[p * 2 + 1][0] = r4[2]; bhf[p * 2 + 1][1] = r4[3];
            }
#pragma unroll
            for (int mi = 0; mi < 4; mi++)
#pragma unroll
                for (int ni = 0; ni < 4; ni++)
                    mma_f16(acc[mi][ni], ah[mi], bhf[ni]);
#pragma unroll
            for (int p = 0; p < 2; p++) {
                uint32_t r4[4];
                ldmatrix_x4(r4, st + OFF_BL + (brow + p * 16) * ROWB + bcolb);
                blf[p * 2][0] = r4[0]; blf[p * 2][1] = r4[1];
                blf[p * 2 + 1][0] = r4[2]; blf[p * 2 + 1][1] = r4[3];
            }
#pragma unroll
            for (int mi = 0; mi < 4; mi++)
#pragma unroll
                for (int ni = 0; ni < 4; ni++)
                    mma_f16(acc[mi][ni], ah[mi], blf[ni]);
        }

        if (kc < 31) {   // convert+store next A chunk into other stage
            char* stn = smem + ((kc + 1) & 1) * STAGE_BYTES;
#pragma unroll
            for (int i = 0; i < 4; i++) {
                int idx = tid + i * 256;
                int r = idx >> 3, g = idx & 7;
                float4 v = av[i];
                uint2 hv;
                hv.x = pack_f16x2(v.x, v.y);
                hv.y = pack_f16x2(v.z, v.w);
                *(uint2*)(stn + OFF_A + r * ROWB + g * 8) = hv;
            }
        }
    }

    // ---- epilogue: acc + bias -> single fp16 ----
#pragma unroll
    for (int mi = 0; mi < 4; mi++) {
        const int r0 = m0 + wm * 64 + mi * 16 + (lane >> 2);
#pragma unroll
        for (int ni = 0; ni < 4; ni++) {
            const int col = n0 + wn * 32 + ni * 8 + (lane & 3) * 2;
            const float b0 = bias[col], b1 = bias[col + 1];
            *(uint32_t*)&C16[(size_t)r0 * DM + col] =
                pack_f16x2(acc[mi][ni][0] + b0, acc[mi][ni][1] + b1);
            *(uint32_t*)&C16[(size_t)(r0 + 8) * DM + col] =
                pack_f16x2(acc[mi][ni][2] + b0, acc[mi][ni][3] + b1);
        }
    }
}

// ---------------------------------------------------------------------------
// GEMM variant 2 (output projection): single fp16 A via cp.async,
// B hi/lo, fp32 C out + bias.
// ---------------------------------------------------------------------------
__global__ __launch_bounds__(256, 1)
void gemm_in16_out32(const __half* __restrict__ A16,
                     const __half* __restrict__ Bhi,
                     const __half* __restrict__ Blo,
                     const float* __restrict__ bias,
                     float* __restrict__ C)
{
    extern __shared__ char smem[];
    const uint32_t smem_base = smem_to_u32(smem);
    const int tid  = threadIdx.x;
    const int wid  = tid >> 5;
    const int lane = tid & 31;
    const int wm   = wid >> 2;
    const int wn   = wid & 3;
    const int m0   = blockIdx.y * 128;
    const int n0   = blockIdx.x * 128;

    float acc[4][4][4];
#pragma unroll
    for (int i = 0; i < 4; i++)
#pragma unroll
        for (int j = 0; j < 4; j++)
#pragma unroll
            for (int k = 0; k < 4; k++) acc[i][j][k] = 0.f;

    {
        const uint32_t st = smem_base;
#pragma unroll
        for (int i = 0; i < 2; i++) {
            int idx = tid + i * 256;          // 512 pieces of A
            int r = idx >> 2, p = idx & 3;
            cp_async16(st + OFF_A + r * ROWB + p * 16,
                       A16 + (size_t)(m0 + r) * DM + p * 8);
        }
#pragma unroll
        for (int i = 0; i < 4; i++) {
            int idx = tid + i * 256;          // 1024 pieces of B hi/lo
            int half_ = idx >> 9, j = idx & 511;
            int r = j >> 2, p = j & 3;
            const __half* src = (half_ ? Blo : Bhi) + (size_t)(n0 + r) * DM + p * 8;
            cp_async16(st + OFF_BH + half_ * 10240 + r * ROWB + p * 16, src);
        }
        cp_async_commit();
    }

    for (int kc = 0; kc < 32; kc++) {
        const uint32_t st = smem_base + (kc & 1) * STAGE_BYTES;

        if (kc < 31) {
            const uint32_t stn = smem_base + ((kc + 1) & 1) * STAGE_BYTES;
#pragma unroll
            for (int i = 0; i < 2; i++) {
                int idx = tid + i * 256;
                int r = idx >> 2, p = idx & 3;
                cp_async16(stn + OFF_A + r * ROWB + p * 16,
                           A16 + (size_t)(m0 + r) * DM + (kc + 1) * 32 + p * 8);
            }
#pragma unroll
            for (int i = 0; i < 4; i++) {
                int idx = tid + i * 256;
                int half_ = idx >> 9, j = idx & 511;
                int r = j >> 2, p = j & 3;
                const __half* src = (half_ ? Blo : Bhi)
                    + (size_t)(n0 + r) * DM + (kc + 1) * 32 + p * 8;
                cp_async16(stn + OFF_BH + half_ * 10240 + r * ROWB + p * 16, src);
            }
            cp_async_commit();
            cp_async_wait1();
        } else {
            cp_async_wait0();
        }
        __syncthreads();

        const int arow  = wm * 64 + (lane & 15);
        const int acolb0 = (lane >> 4) * 16;
        const int bg    = lane >> 3;
        const int brow  = wn * 32 + ((bg & 2) ? 8 : 0) + (lane & 7);
        const int bcolb0 = (bg & 1) * 16;
#pragma unroll
        for (int ks = 0; ks < 2; ks++) {
            const int acolb = ks * 32 + acolb0;
            const int bcolb = ks * 32 + bcolb0;
            uint32_t ah[4][4], bhf[4][2], blf[4][2];
#pragma unroll
            for (int mi = 0; mi < 4; mi++)
                ldmatrix_x4(ah[mi], st + OFF_A + (arow + mi * 16) * ROWB + acolb);
#pragma unroll
            for (int p = 0; p < 2; p++) {
                uint32_t r4[4];
                ldmatrix_x4(r4, st + OFF_BH + (brow + p * 16) * ROWB + bcolb);
                bhf[p * 2][0] = r4[0]; bhf[p * 2][1] = r4[1];
                bhf[p * 2 + 1][0] = r4[2]; bhf[p * 2 + 1][1] = r4[3];
            }
#pragma unroll
            for (int mi = 0; mi < 4; mi++)
#pragma unroll
                for (int ni = 0; ni < 4; ni++)
                    mma_f16(acc[mi][ni], ah[mi], bhf[ni]);
#pragma unroll
            for (int p = 0; p < 2; p++) {
                uint32_t r4[4];
                ldmatrix_x4(r4, st + OFF_BL + (brow + p * 16) * ROWB + bcolb);
                blf[p * 2][0] = r4[0]; blf[p * 2][1] = r4[1];
                blf[p * 2 + 1][0] = r4[2]; blf[p * 2 + 1][1] = r4[3];
            }
#pragma unroll
            for (int mi = 0; mi < 4; mi++)
#pragma unroll
                for (int ni = 0; ni < 4; ni++)
                    mma_f16(acc[mi][ni], ah[mi], blf[ni]);
        }
        __syncthreads();
    }

#pragma unroll
    for (int mi = 0; mi < 4; mi++) {
        const int r0 = m0 + wm * 64 + mi * 16 + (lane >> 2);
#pragma unroll
        for (int ni = 0; ni < 4; ni++) {
            const int col = n0 + wn * 32 + ni * 8 + (lane & 3) * 2;
            const float b0 = bias[col], b1 = bias[col + 1];
            float2 v0 = {acc[mi][ni][0] + b0, acc[mi][ni][1] + b1};
            float2 v1 = {acc[mi][ni][2] + b0, acc[mi][ni][3] + b1};
            *(float2*)(C + (size_t)r0 * DM + col) = v0;
            *(float2*)(C + (size_t)(r0 + 8) * DM + col) = v1;
        }
    }
}

// ---------------------------------------------------------------------------
// Flash attention v4 — pure fp16 HMMA (1 MMA term per GEMM),
// cp.async double-buffered K/V, single-fp16 intermediates.
// ---------------------------------------------------------------------------
#define AROWB 144
#define AQ 0
#define AST0 (128 * AROWB)                  // 18432
#define TILE_B (64 * AROWB)                 // 9216 ; stage = K tile + V tile
#define ATTN_SMEM (AST0 + 2 * 2 * TILE_B)   // 55296

__global__ __launch_bounds__(256)
void attention_f16_kernel(const __half* __restrict__ Q16,
                          const __half* __restrict__ K16,
                          const __half* __restrict__ V16,
                          __half* __restrict__ A16)
{
    extern __shared__ char smem[];
    const uint32_t smem_base = smem_to_u32(smem);
    const int tid  = threadIdx.x;
    const int wid  = tid >> 5;
    const int lane = tid & 31;
    const int b    = blockIdx.z;
    const int h    = blockIdx.y;
    const int q0   = blockIdx.x * 128;

    const size_t tok0 = (size_t)b * 1024;
    const int colbase = h * DH;

    // ---- prologue: stage Q + K/V tile 0 ----
    {
#pragma unroll
        for (int i = 0; i < 4; i++) {
            int idx = tid + i * 256;          // 1024 pieces (128 rows x 8)
            int r = idx >> 3, p = idx & 7;
            cp_async16(smem_base + AQ + r * AROWB + p * 16,
                       Q16 + (tok0 + q0 + r) * DM + colbase + p * 8);
        }
        const __half* srcs[2] = { K16 + tok0 * DM + colbase,
                                  V16 + tok0 * DM + colbase };
#pragma unroll
        for (int i = 0; i < 4; i++) {
            int idx = tid + i * 256;          // 1024 pieces (2 tiles x 64 x 8)
            int tv = idx >> 9, j = idx & 511;
            int r = j >> 3, p = j & 7;
            cp_async16(smem_base + AST0 + tv * TILE_B + r * AROWB + p * 16,
                       srcs[tv] + (size_t)r * DM + p * 8);
        }
        cp_async_commit();
    }

    float oacc[8][4];
    float mrow[2], lrow[2];
#pragma unroll
    for (int t = 0; t < 8; t++)
#pragma unroll
        for (int c = 0; c < 4; c++) oacc[t][c] = 0.f;
    mrow[0] = mrow[1] = -1e30f;
    lrow[0] = lrow[1] = 0.f;

    const uint32_t aQ = smem_base + AQ + (wid * 16 + (lane & 15)) * AROWB + (lane >> 4) * 16;
    const int bg = lane >> 3;
    const int brow_off = ((bg & 2) ? 8 : 0) + (lane & 7);
    const int bcolb = (bg & 1) * 16;
    const uint32_t vrow_addr = (lane & 15) * AROWB + (lane >> 4) * 16;

    for (int kt = 0; kt < 16; kt++) {
        const uint32_t stg = smem_base + AST0 + (kt & 1) * (2 * TILE_B);

        if (kt < 15) {
            const uint32_t stgn = smem_base + AST0 + ((kt + 1) & 1) * (2 * TILE_B);
            const size_t t0 = tok0 + (size_t)(kt + 1) * 64;
            const __half* srcs[2] = { K16 + t0 * DM + colbase,
                                      V16 + t0 * DM + colbase };
#pragma unroll
            for (int i = 0; i < 4; i++) {
                int idx = tid + i * 256;
                int tv = idx >> 9, j = idx & 511;
                int r = j >> 3, p = j & 7;
                cp_async16(stgn + tv * TILE_B + r * AROWB + p * 16,
                           srcs[tv] + (size_t)r * DM + p * 8);
            }
            cp_async_commit();
            cp_async_wait1();
        } else {
            cp_async_wait0();
        }
        __syncthreads();

        // ---- S = Q K^T (1 term) ----
        float sacc[8][4];
#pragma unroll
        for (int t = 0; t < 8; t++)
#pragma unroll
            for (int c = 0; c < 4; c++) sacc[t][c] = 0.f;

#pragma unroll
        for (int ks = 0; ks < 4; ks++) {
            uint32_t qf[4];
            ldmatrix_x4(qf, aQ + ks * 32);
#pragma unroll
            for (int nt = 0; nt < 4; nt++) {
                uint32_t kf[4];
                ldmatrix_x4(kf, stg + (nt * 16 + brow_off) * AROWB + ks * 32 + bcolb);
                mma_f16(sacc[2 * nt],     qf, kf + 0);
                mma_f16(sacc[2 * nt + 1], qf, kf + 2);
            }
        }

        // ---- online softmax ----
#pragma unroll
        for (int half_ = 0; half_ < 2; half_++) {
            const int c0 = half_ * 2;
            float rm = -1e30f;
#pragma unroll
            for (int t = 0; t < 8; t++) {
                sacc[t][c0]     *= 0.125f;
                sacc[t][c0 + 1] *= 0.125f;
                rm = fmaxf(rm, fmaxf(sacc[t][c0], sacc[t][c0 + 1]));
            }
            rm = fmaxf(rm, __shfl_xor_sync(0xffffffffu, rm, 1));
            rm = fmaxf(rm, __shfl_xor_sync(0xffffffffu, rm, 2));
            float mnew = fmaxf(mrow[half_], rm);
            float corr = __expf(mrow[half_] - mnew);
            mrow[half_] = mnew;
            float rs = 0.f;
#pragma unroll
            for (int t = 0; t < 8; t++) {
                float p0 = __expf(sacc[t][c0] - mnew);
                float p1 = __expf(sacc[t][c0 + 1] - mnew);
                sacc[t][c0] = p0;
                sacc[t][c0 + 1] = p1;
                rs += p0 + p1;
            }
            rs += __shfl_xor_sync(0xffffffffu, rs, 1);
            rs += __shfl_xor_sync(0xffffffffu, rs, 2);
            lrow[half_] = lrow[half_] * corr + rs;
#pragma unroll
            for (int t = 0; t < 8; t++) {
                oacc[t][c0]     *= corr;
                oacc[t][c0 + 1] *= corr;
            }
        }

        // ---- O += P V (1 term) ----
#pragma unroll
        for (int j = 0; j < 4; j++) {
            uint32_t pf[4];
#pragma unroll
            for (int q = 0; q < 4; q++) {
                const int t = 2 * j + (q >> 1);
                const int c = (q & 1) * 2;
                pf[q] = pack_f16x2(sacc[t][c], sacc[t][c + 1]);
            }
#pragma unroll
            for (int nt = 0; nt < 4; nt++) {
                uint32_t vf[4];
                ldmatrix_x4_trans(vf, stg + TILE_B + (j * 16) * AROWB + nt * 32 + vrow_addr);
                mma_f16(oacc[2 * nt],     pf, vf + 0);
                mma_f16(oacc[2 * nt + 1], pf, vf + 2);
            }
        }
        __syncthreads();
    }

    // ---- normalize + write attn (single fp16) ----
    const float inv0 = 1.f / lrow[0];
    const float inv1 = 1.f / lrow[1];
    const int row0 = q0 + wid * 16 + (lane >> 2);
#pragma unroll
    for (int t = 0; t < 8; t++) {
        const int col = colbase + t * 8 + (lane & 3) * 2;
        *(uint32_t*)&A16[(tok0 + row0) * DM + col] =
            pack_f16x2(oacc[t][0] * inv0, oacc[t][1] * inv0);
        *(uint32_t*)&A16[(tok0 + row0 + 8) * DM + col] =
            pack_f16x2(oacc[t][2] * inv1, oacc[t][3] * inv1);
    }
}

// ---------------------------------------------------------------------------
extern "C" void kernel_launch(void* const* d_in, const int* in_sizes, int n_in,
                              void* d_out, int out_size)
{
    const float* q_in = (const float*)d_in[0];
    const float* k_in = (const float*)d_in[1];
    const float* v_in = (const float*)d_in[2];
    const float* Wq   = (const float*)d_in[3];
    const float* bq   = (const float*)d_in[4];
    const float* Wk   = (const float*)d_in[5];
    const float* bk   = (const float*)d_in[6];
    const float* Wv   = (const float*)d_in[7];
    const float* bv   = (const float*)d_in[8];
    const float* Wo   = (const float*)d_in[9];
    const float* bo   = (const float*)d_in[10];

    __half *pq, *pk, *pv, *pa;
    cudaGetSymbolAddress((void**)&pq, g_q16);
    cudaGetSymbolAddress((void**)&pk, g_k16);
    cudaGetSymbolAddress((void**)&pv, g_v16);
    cudaGetSymbolAddress((void**)&pa, g_a16);
    __half *wqh, *wql, *wkh, *wkl, *wvh, *wvl, *woh, *wol;
    cudaGetSymbolAddress((void**)&wqh, g_wq_hi);
    cudaGetSymbolAddress((void**)&wql, g_wq_lo);
    cudaGetSymbolAddress((void**)&wkh, g_wk_hi);
    cudaGetSymbolAddress((void**)&wkl, g_wk_lo);
    cudaGetSymbolAddress((void**)&wvh, g_wv_hi);
    cudaGetSymbolAddress((void**)&wvl, g_wv_lo);
    cudaGetSymbolAddress((void**)&woh, g_wo_hi);
    cudaGetSymbolAddress((void**)&wol, g_wo_lo);

    cudaFuncSetAttribute(gemm_in32_out16,
                         cudaFuncAttributeMaxDynamicSharedMemorySize, GEMM_SMEM);
    cudaFuncSetAttribute(gemm_in16_out32,
                         cudaFuncAttributeMaxDynamicSharedMemorySize, GEMM_SMEM);
    cudaFuncSetAttribute(attention_f16_kernel,
                         cudaFuncAttributeMaxDynamicSharedMemorySize, ATTN_SMEM);

    dim3 tg(32, 32), tb(32, 8);
    transpose_w_kernel<<<tg, tb>>>(Wq, wqh, wql);
    transpose_w_kernel<<<tg, tb>>>(Wk, wkh, wkl);
    transpose_w_kernel<<<tg, tb>>>(Wv, wvh, wvl);
    transpose_w_kernel<<<tg, tb>>>(Wo, woh, wol);

    dim3 gg(DM / 128, MTOT / 128);   // (8, 32)
    gemm_in32_out16<<<gg, 256, GEMM_SMEM>>>(q_in, wqh, wql, bq, pq);
    gemm_in32_out16<<<gg, 256, GEMM_SMEM>>>(k_in, wkh, wkl, bk, pk);
    gemm_in32_out16<<<gg, 256, GEMM_SMEM>>>(v_in, wvh, wvl, bv, pv);

    attention_f16_kernel<<<dim3(8, 16, 4), 256, ATTN_SMEM>>>(pq, pk, pv, pa);

    gemm_in16_out32<<<gg, 256, GEMM_SMEM>>>(pa, woh, wol, bo, (float*)d_out);
}